// round 10
// baseline (speedup 1.0000x reference)
#include <cuda_runtime.h>
#include <cuda_fp16.h>
#include <math.h>
#include <stdint.h>

#define B_  2
#define S_  2048
#define D_  1024
#define H_  16
#define HD  64

// ---------------- scratch (device globals) ----------------
__device__ float g_cos[S_*32];
__device__ float g_sin[S_*32];
// fp16 packed pairs-along-K as uint32. A-side: hi+lo. B-side: hi only.
__device__ uint32_t g_xhi[B_*S_*D_/2],  g_xlo[B_*S_*D_/2];
__device__ uint32_t g_wqh[3*D_*D_/2];                       // transposed [N][K]
__device__ uint32_t g_woh[D_*D_/2];                         // transposed [N][K]
__device__ uint32_t g_qhi[B_*H_*S_*HD/2], g_qlo[B_*H_*S_*HD/2];
__device__ uint32_t g_khi[B_*H_*S_*HD/2];
__device__ uint32_t g_vhi[B_*H_*S_*HD/2];                   // V in K-layout [s][d]
__device__ uint32_t g_yhi[B_*S_*D_/2],  g_ylo[B_*S_*D_/2];

// ---------------- helpers ----------------
__device__ __forceinline__ float hhi(float v) {
    return __half2float(__float2half_rn(v));
}
__device__ __forceinline__ uint32_t packh(float f_low, float f_high) {
    uint32_t r;
    asm("cvt.rn.f16x2.f32 %0, %1, %2;" : "=r"(r) : "f"(f_high), "f"(f_low));
    return r;
}
__device__ __forceinline__ float fexp2(float x) {
    float r;
    asm("ex2.approx.f32 %0, %1;" : "=f"(r) : "f"(x));
    return r;
}
__device__ __forceinline__ void cp16(void* dst, const void* src) {
    uint32_t d = (uint32_t)__cvta_generic_to_shared(dst);
    asm volatile("cp.async.cg.shared.global [%0], [%1], 16;\n" :: "r"(d), "l"(src));
}
__device__ __forceinline__ void cp_commit() {
    asm volatile("cp.async.commit_group;\n");
}
template<int N> __device__ __forceinline__ void cp_wait() {
    asm volatile("cp.async.wait_group %0;\n" :: "n"(N));
}
__device__ __forceinline__ void mma_f16(float* d, const uint32_t* a, const uint32_t* b) {
    asm volatile(
        "mma.sync.aligned.m16n8k16.row.col.f32.f16.f16.f32 "
        "{%0,%1,%2,%3}, {%4,%5,%6,%7}, {%8,%9}, {%0,%1,%2,%3};\n"
        : "+f"(d[0]), "+f"(d[1]), "+f"(d[2]), "+f"(d[3])
        : "r"(a[0]), "r"(a[1]), "r"(a[2]), "r"(a[3]), "r"(b[0]), "r"(b[1]));
}
__device__ __forceinline__ void ldsm4(uint32_t* r, uint32_t saddr) {
    asm volatile("ldmatrix.sync.aligned.m8n8.x4.shared.b16 {%0,%1,%2,%3}, [%4];"
        : "=r"(r[0]), "=r"(r[1]), "=r"(r[2]), "=r"(r[3]) : "r"(saddr));
}
__device__ __forceinline__ void ldsm4t(uint32_t* r, uint32_t saddr) {
    asm volatile("ldmatrix.sync.aligned.m8n8.x4.trans.shared.b16 {%0,%1,%2,%3}, [%4];"
        : "=r"(r[0]), "=r"(r[1]), "=r"(r[2]), "=r"(r[3]) : "r"(saddr));
}

#define QSC_ (0.125f * 1.44269504088896340736f)   // 1/sqrt(64) * log2(e)

// ---------------- RoPE table ----------------
__global__ void rope_table_kernel() {
    int idx = blockIdx.x * 256 + threadIdx.x;
    if (idx >= S_ * 32) return;
    int s = idx >> 5;
    int j = idx & 31;
    double inv = pow(10000.0, -((double)(2 * j)) / 64.0);
    double ang = (double)s * inv;
    g_cos[idx] = (float)cos(ang);
    g_sin[idx] = (float)sin(ang);
}

// ---------------- elementwise fp16 hi/lo split (packed pairs) ----------------
__global__ __launch_bounds__(256) void split2_kernel(
    const float* __restrict__ src, uint32_t* __restrict__ hi, uint32_t* __restrict__ lo, int n2)
{
    int i = blockIdx.x * 256 + threadIdx.x;
    if (i >= n2) return;
    float2 v = ((const float2*)src)[i];
    float h0 = hhi(v.x), h1 = hhi(v.y);
    hi[i] = packh(h0, h1);
    lo[i] = packh(v.x - h0, v.y - h1);
}

// ---------------- weight transpose + fp16 quantize: w[K][N] -> wt[N][K] ----------------
__global__ __launch_bounds__(256) void wsplit_t_kernel(
    const float* __restrict__ w, uint32_t* __restrict__ th, int Kd, int Nd)
{
    __shared__ float tile[32][33];
    int n0 = blockIdx.x * 32, k0 = blockIdx.y * 32;
    int tx = threadIdx.x & 31, ty = threadIdx.x >> 5;
    #pragma unroll
    for (int r = 0; r < 32; r += 8)
        tile[ty + r][tx] = w[(size_t)(k0 + ty + r) * Nd + n0 + tx];
    __syncthreads();
    __half* thb = (__half*)th;
    #pragma unroll
    for (int r = 0; r < 32; r += 8) {
        int n = n0 + ty + r, k = k0 + tx;
        thb[(size_t)n * Kd + k] = __float2half_rn(tile[tx][ty + r]);
    }
}

// ---------------- shared GEMM plumbing ----------------
#define KS 20
#define G_AH 0
#define G_AL 2560
#define G_BH 5120
#define G_STAGE 7680
#define SMEM_GEMM_U32 (3*G_STAGE)

__device__ __forceinline__ void gemm_stage_load(
    uint32_t* st, const uint32_t* Ah, const uint32_t* Al, const uint32_t* Bh,
    int kp0, int tid, int Kp)
{
    const int row = tid >> 1;
    const int c = (tid & 1) * 8;
    const size_t ga = (size_t)row * Kp + kp0 + c;
    cp16(&st[G_AH + row * KS + c],     Ah + ga);
    cp16(&st[G_AH + row * KS + c + 4], Ah + ga + 4);
    cp16(&st[G_AL + row * KS + c],     Al + ga);
    cp16(&st[G_AL + row * KS + c + 4], Al + ga + 4);
    cp16(&st[G_BH + row * KS + c],     Bh + ga);
    cp16(&st[G_BH + row * KS + c + 4], Bh + ga + 4);
}

// mainloop macro body shared by both GEMMs (expands in-function)
#define GEMM_MAINLOOP(ACC)                                                              \
    const int NT = Kp / 16;                                                             \
    gemm_stage_load(smg, Ahi, Alo, Bhi, 0, tid, Kp);                                    \
    cp_commit();                                                                        \
    gemm_stage_load(smg + G_STAGE, Ahi, Alo, Bhi, 16, tid, Kp);                         \
    cp_commit();                                                                        \
    int stage = 0;                                                                      \
    for (int it = 0; it < NT; it++) {                                                   \
        cp_wait<1>();                                                                   \
        __syncthreads();                                                                \
        if (it + 2 < NT) {                                                              \
            int s2 = stage + 2; if (s2 >= 3) s2 -= 3;                                   \
            gemm_stage_load(smg + s2 * G_STAGE, Ahi, Alo, Bhi, (it + 2) * 16, tid, Kp); \
        }                                                                               \
        cp_commit();                                                                    \
        const uint32_t stB = smB + (stage * G_STAGE) * 4;                               \
        _Pragma("unroll")                                                               \
        for (int kstep = 0; kstep < 2; kstep++) {                                       \
            const int k8 = kstep * 8;                                                   \
            uint32_t ah[2][4], al[2][4];                                                \
            _Pragma("unroll")                                                           \
            for (int mt = 0; mt < 2; mt++) {                                            \
                const uint32_t ab = stB + ((G_AH + (mBase + mt*16 + aR)*KS + k8 + aC) << 2); \
                ldsm4(ah[mt], ab);                                                      \
                ldsm4(al[mt], ab + (G_AL - G_AH) * 4);                                  \
            }                                                                           \
            _Pragma("unroll")                                                           \
            for (int ntp = 0; ntp < 4; ntp++) {                                         \
                uint32_t bb[4];                                                         \
                ldsm4(bb, stB + ((G_BH + (nBase + ntp*16 + bR)*KS + k8 + bC) << 2));    \
                _Pragma("unroll")                                                       \
                for (int mt = 0; mt < 2; mt++) {                                        \
                    mma_f16(ACC[mt][2*ntp],     ah[mt], bb);                            \
                    mma_f16(ACC[mt][2*ntp],     al[mt], bb);                            \
                    mma_f16(ACC[mt][2*ntp + 1], ah[mt], bb + 2);                        \
                    mma_f16(ACC[mt][2*ntp + 1], al[mt], bb + 2);                        \
                }                                                                       \
            }                                                                           \
        }                                                                               \
        if (++stage == 3) stage = 0;                                                    \
    }

// ---------------- QKV GEMM with fused RoPE + fp16 split epilogue ----------------
__global__ __launch_bounds__(256, 2) void qkv_gemm_rope_kernel(
    const uint32_t* __restrict__ Ahi, const uint32_t* __restrict__ Alo,
    const uint32_t* __restrict__ Bhi)
{
    extern __shared__ uint32_t smg[];
    const int Kp = D_ >> 1;
    const int tid  = threadIdx.x;
    const int warp = tid >> 5;
    const int lane = tid & 31;
    const int g = lane >> 2;
    const int t = lane & 3;
    const int mBase = (warp >> 1) * 32;
    const int nBase = (warp & 1) * 64;

    const int r8 = lane & 7;
    const int aR = ((lane >> 3) & 1) * 8 + r8;
    const int aC = ((lane >> 4) & 1) * 4;
    const int bR = ((lane >> 4) & 1) * 8 + r8;
    const int bC = ((lane >> 3) & 1) * 4;
    const uint32_t smB = (uint32_t)__cvta_generic_to_shared(smg);

    Ahi += (size_t)blockIdx.y * 128 * Kp;
    Alo += (size_t)blockIdx.y * 128 * Kp;
    Bhi += (size_t)blockIdx.x * 128 * Kp;

    float acc[2][8][4];
    #pragma unroll
    for (int mt = 0; mt < 2; mt++)
        #pragma unroll
        for (int nt = 0; nt < 8; nt++)
            #pragma unroll
            for (int r = 0; r < 4; r++) acc[mt][nt][r] = 0.f;

    GEMM_MAINLOOP(acc)

    // ---- fused epilogue: RoPE (q,k) + fp16 split, V passthrough quantize ----
    const int gcolbase = blockIdx.x * 128 + nBase;   // multiple of 64
    const int region = gcolbase >> 10;               // 0=q 1=k 2=v
    const int head   = (gcolbase & 1023) >> 6;

    #pragma unroll
    for (int mt = 0; mt < 2; mt++) {
        #pragma unroll
        for (int rs = 0; rs < 2; rs++) {
            const int m = blockIdx.y * 128 + mBase + mt * 16 + g + rs * 8;
            const int b = m >> 11, s = m & 2047;
            const size_t dbase = ((size_t)(b * 16 + head) * S_ + s) * 32;
            if (region == 2) {
                #pragma unroll
                for (int nt = 0; nt < 8; nt++) {
                    float v0 = acc[mt][nt][rs * 2 + 0];
                    float v1 = acc[mt][nt][rs * 2 + 1];
                    g_vhi[dbase + nt * 4 + t] = packh(hhi(v0), hhi(v1));
                }
            } else {
                #pragma unroll
                for (int nt = 0; nt < 8; nt++) {
                    const int i0 = nt * 8 + t * 2;
                    const int j0 = i0 & 31;
                    float c0 = g_cos[s * 32 + j0], c1 = g_cos[s * 32 + j0 + 1];
                    float s0 = g_sin[s * 32 + j0], s1 = g_sin[s * 32 + j0 + 1];
                    float sg = (i0 < 32) ? -1.f : 1.f;
                    float v0 = acc[mt][nt][rs * 2 + 0];
                    float v1 = acc[mt][nt][rs * 2 + 1];
                    float p0 = acc[mt][nt ^ 4][rs * 2 + 0];
                    float p1 = acc[mt][nt ^ 4][rs * 2 + 1];
                    float r0 = v0 * c0 + sg * p0 * s0;
                    float r1 = v1 * c1 + sg * p1 * s1;
                    if (region == 0) {
                        r0 *= QSC_; r1 *= QSC_;
                        float h0 = hhi(r0), h1 = hhi(r1);
                        g_qhi[dbase + nt * 4 + t] = packh(h0, h1);
                        g_qlo[dbase + nt * 4 + t] = packh(r0 - h0, r1 - h1);
                    } else {
                        g_khi[dbase + nt * 4 + t] = packh(hhi(r0), hhi(r1));
                    }
                }
            }
        }
    }
}

// ---------------- generic fp16 2-product GEMM (O-proj) ----------------
__global__ __launch_bounds__(256, 2) void f16_gemm_kernel(
    const uint32_t* __restrict__ Ahi, const uint32_t* __restrict__ Alo,
    const uint32_t* __restrict__ Bhi,
    float* __restrict__ C, int M, int N, int K)
{
    extern __shared__ uint32_t smg[];
    const int Kp = K >> 1;
    const int tid  = threadIdx.x;
    const int warp = tid >> 5;
    const int lane = tid & 31;
    const int g = lane >> 2;
    const int t = lane & 3;
    const int mBase = (warp >> 1) * 32;
    const int nBase = (warp & 1) * 64;

    const int r8 = lane & 7;
    const int aR = ((lane >> 3) & 1) * 8 + r8;
    const int aC = ((lane >> 4) & 1) * 4;
    const int bR = ((lane >> 4) & 1) * 8 + r8;
    const int bC = ((lane >> 3) & 1) * 4;
    const uint32_t smB = (uint32_t)__cvta_generic_to_shared(smg);

    Ahi += (size_t)blockIdx.y * 128 * Kp;
    Alo += (size_t)blockIdx.y * 128 * Kp;
    Bhi += (size_t)blockIdx.x * 128 * Kp;

    float acc[2][8][4];
    #pragma unroll
    for (int mt = 0; mt < 2; mt++)
        #pragma unroll
        for (int nt = 0; nt < 8; nt++)
            #pragma unroll
            for (int r = 0; r < 4; r++) acc[mt][nt][r] = 0.f;

    GEMM_MAINLOOP(acc)

    C += (size_t)blockIdx.y * 128 * N + blockIdx.x * 128;
    #pragma unroll
    for (int mt = 0; mt < 2; mt++) {
        const int r0 = mBase + mt * 16 + g;
        #pragma unroll
        for (int nt = 0; nt < 8; nt++) {
            const int c = nBase + nt * 8 + t * 2;
            *(float2*)&C[(size_t)r0 * N + c]       = make_float2(acc[mt][nt][0], acc[mt][nt][1]);
            *(float2*)&C[(size_t)(r0 + 8) * N + c] = make_float2(acc[mt][nt][2], acc[mt][nt][3]);
        }
    }
}

// ---------------- fp16 tensor-core causal flash attention ----------------
#define APS 36
#define A_PH 0
#define A_PL 4608
#define A_KV 9216
#define KV_KH 0
#define KV_VH 2304
#define KV_STAGE 4608
#define A_MSK (A_KV + 2*KV_STAGE)
#define SMEM_ATTN_U32 (A_MSK + S_)

__device__ __forceinline__ void attn_stage_load(
    uint32_t* sma, int st, const uint32_t* kh, const uint32_t* vh, int kt, int tid)
{
    uint32_t* base = sma + A_KV + st * KV_STAGE;
    const int r = tid >> 2, c = tid & 3;
    const size_t gk = (size_t)(kt * 64 + r) * 32;
    cp16(&base[KV_KH + r * APS + c * 4],       kh + gk + c * 4);
    cp16(&base[KV_KH + r * APS + (c + 4) * 4], kh + gk + (c + 4) * 4);
    cp16(&base[KV_VH + r * APS + c * 4],       vh + gk + c * 4);
    cp16(&base[KV_VH + r * APS + (c + 4) * 4], vh + gk + (c + 4) * 4);
}

__global__ __launch_bounds__(256, 2) void attn_tc_kernel(const int* __restrict__ amask) {
    extern __shared__ uint32_t sma[];
    uint32_t* sPh = sma + A_PH;
    uint32_t* sPl = sma + A_PL;
    float* sMf = (float*)(sma + A_MSK);

    const int tid  = threadIdx.x;
    const int warp = tid >> 5;
    const int lane = tid & 31;
    const int g = lane >> 2;
    const int t = lane & 3;
    // LPT ordering: heaviest q-tiles first
    const int qtile = (S_ / 128 - 1) - (int)(blockIdx.x >> 5);
    const int bh    = blockIdx.x & 31;
    const int b  = bh >> 4;
    const int h  = bh & 15;
    const int qbase = qtile * 128;
    const int wrow  = warp * 16;

    const int r8 = lane & 7;
    const int aR = ((lane >> 3) & 1) * 8 + r8;
    const int aC = ((lane >> 4) & 1) * 4;
    const int bR = ((lane >> 4) & 1) * 8 + r8;
    const int bC = ((lane >> 3) & 1) * 4;
    // trans-ldmatrix lane mapping for V [k][n] tiles
    const int vR = ((lane >> 3) & 1) * 8 + r8;
    const int vC = ((lane >> 4) & 1) * 4;
    const uint32_t smB = (uint32_t)__cvta_generic_to_shared(sma);

    const uint32_t* kh = g_khi + (size_t)bh * S_ * 32;
    const uint32_t* vh = g_vhi + (size_t)bh * S_ * 32;

    const int nkt = (qbase + 128) / 64;

    attn_stage_load(sma, 0, kh, vh, 0, tid);
    cp_commit();

    {
        const uint32_t* qgh = g_qhi + ((size_t)bh * S_ + qbase) * 32;
        const uint32_t* qgl = g_qlo + ((size_t)bh * S_ + qbase) * 32;
        for (int idx = tid; idx < 1024; idx += 256) {
            int r = idx >> 3, c4 = (idx & 7) * 4;
            *(uint4*)&sPh[r * APS + c4] = *(const uint4*)(qgh + r * 32 + c4);
            *(uint4*)&sPl[r * APS + c4] = *(const uint4*)(qgl + r * 32 + c4);
        }
        for (int idx = tid; idx < S_; idx += 256)
            sMf[idx] = (amask[b * S_ + idx] == 0) ? -INFINITY : 0.f;
    }
    __syncthreads();

    uint32_t Qh[4][4], Ql[4][4];
    #pragma unroll
    for (int ks = 0; ks < 4; ks++) {
        const uint32_t qaddr = smB + (((wrow + aR) * APS + ks * 8 + aC) << 2);
        ldsm4(Qh[ks], qaddr);
        ldsm4(Ql[ks], qaddr + A_PL * 4);
    }
    // each warp reads/writes only its own 16 sP rows from here on

    float oacc[8][4];
    #pragma unroll
    for (int nt = 0; nt < 8; nt++)
        #pragma unroll
        for (int r = 0; r < 4; r++) oacc[nt][r] = 0.f;
    float mrun[2] = {-INFINITY, -INFINITY};
    float lrun[2] = {0.f, 0.f};

    for (int kt = 0; kt < nkt; kt++) {
        if (kt + 1 < nkt) {
            attn_stage_load(sma, (kt + 1) & 1, kh, vh, kt + 1, tid);
            cp_commit();
            cp_wait<1>();
        } else {
            cp_wait<0>();
        }
        __syncthreads();

        if (kt * 64 <= qbase + wrow + 15) {
            const uint32_t kvB = smB + ((A_KV + (kt & 1) * KV_STAGE) << 2);

            // ---- S = Q K^T ----
            float sacc[8][4];
            #pragma unroll
            for (int nt = 0; nt < 8; nt++)
                #pragma unroll
                for (int r = 0; r < 4; r++) sacc[nt][r] = 0.f;

            #pragma unroll
            for (int ks = 0; ks < 4; ks++) {
                #pragma unroll
                for (int ntp = 0; ntp < 4; ntp++) {
                    uint32_t bb[4];
                    ldsm4(bb, kvB + ((KV_KH + (ntp * 16 + bR) * APS + ks * 8 + bC) << 2));
                    mma_f16(sacc[2 * ntp],     Qh[ks], bb);
                    mma_f16(sacc[2 * ntp],     Ql[ks], bb);
                    mma_f16(sacc[2 * ntp + 1], Qh[ks], bb + 2);
                    mma_f16(sacc[2 * ntp + 1], Ql[ks], bb + 2);
                }
            }

            // ---- masks + row max (log2 domain) ----
            const bool diag = (kt * 64 + 63) > (qbase + wrow);
            float tmax[2] = {-INFINITY, -INFINITY};
            #pragma unroll
            for (int nt = 0; nt < 8; nt++) {
                #pragma unroll
                for (int e = 0; e < 4; e++) {
                    const int colL = nt * 8 + t * 2 + (e & 1);
                    float v = sacc[nt][e] + sMf[kt * 64 + colL];
                    if (diag) {
                        const int row = qbase + wrow + g + ((e >> 1) << 3);
                        const int col = kt * 64 + colL;
                        if (col > row) v = -INFINITY;
                    }
                    sacc[nt][e] = v;
                    tmax[e >> 1] = fmaxf(tmax[e >> 1], v);
                }
            }
            #pragma unroll
            for (int i = 0; i < 2; i++) {
                tmax[i] = fmaxf(tmax[i], __shfl_xor_sync(0xffffffff, tmax[i], 1));
                tmax[i] = fmaxf(tmax[i], __shfl_xor_sync(0xffffffff, tmax[i], 2));
            }

            // ---- online softmax (base-2) ----
            float corr[2], psum[2] = {0.f, 0.f};
            #pragma unroll
            for (int i = 0; i < 2; i++) {
                float mnew = fmaxf(mrun[i], tmax[i]);
                corr[i] = fexp2(mrun[i] - mnew);
                mrun[i] = mnew;
                lrun[i] *= corr[i];
            }
            #pragma unroll
            for (int nt = 0; nt < 8; nt++) {
                oacc[nt][0] *= corr[0]; oacc[nt][1] *= corr[0];
                oacc[nt][2] *= corr[1]; oacc[nt][3] *= corr[1];
            }
            #pragma unroll
            for (int nt = 0; nt < 8; nt++) {
                #pragma unroll
                for (int half = 0; half < 2; half++) {
                    float p0 = fexp2(sacc[nt][half * 2 + 0] - mrun[half]);
                    float p1 = fexp2(sacc[nt][half * 2 + 1] - mrun[half]);
                    psum[half] += p0 + p1;
                    float h0 = hhi(p0), h1 = hhi(p1);
                    const int row = wrow + g + half * 8;
                    sPh[row * APS + nt * 4 + t] = packh(h0, h1);
                    sPl[row * APS + nt * 4 + t] = packh(p0 - h0, p1 - h1);
                }
            }
            #pragma unroll
            for (int i = 0; i < 2; i++) {
                psum[i] += __shfl_xor_sync(0xffffffff, psum[i], 1);
                psum[i] += __shfl_xor_sync(0xffffffff, psum[i], 2);
                lrun[i] += psum[i];
            }
            __syncwarp();

            // ---- O += P V  (V in [k][n] layout, trans frags) ----
            #pragma unroll
            for (int ks = 0; ks < 4; ks++) {
                uint32_t ph4[4], pl4[4];
                const uint32_t paddr = smB + (((wrow + aR) * APS + ks * 8 + aC) << 2);
                ldsm4(ph4, paddr);
                ldsm4(pl4, paddr + A_PL * 4);
                #pragma unroll
                for (int ntp = 0; ntp < 4; ntp++) {
                    uint32_t vv[4];
                    ldsm4t(vv, kvB + ((KV_VH + (ks * 16 + vR) * APS + ntp * 8 + vC) << 2));
                    mma_f16(oacc[2 * ntp],     ph4, vv);
                    mma_f16(oacc[2 * ntp],     pl4, vv);
                    mma_f16(oacc[2 * ntp + 1], ph4, vv + 2);
                    mma_f16(oacc[2 * ntp + 1], pl4, vv + 2);
                }
            }
            __syncwarp();
        }
        __syncthreads();
    }

    // ---- epilogue: o/l, fp16 split, packed write ----
    const float inv0 = 1.f / lrun[0];
    const float inv1 = 1.f / lrun[1];
    const int r0 = qbase + wrow + g;
    const int r1 = r0 + 8;
    #pragma unroll
    for (int nt = 0; nt < 8; nt++) {
        float v0 = oacc[nt][0] * inv0, v1 = oacc[nt][1] * inv0;
        float v2 = oacc[nt][2] * inv1, v3 = oacc[nt][3] * inv1;
        const size_t o0 = (size_t)(b * S_ + r0) * 512 + h * 32 + nt * 4 + t;
        const size_t o1 = (size_t)(b * S_ + r1) * 512 + h * 32 + nt * 4 + t;
        float h0 = hhi(v0), h1 = hhi(v1), h2 = hhi(v2), h3 = hhi(v3);
        g_yhi[o0] = packh(h0, h1);
        g_ylo[o0] = packh(v0 - h0, v1 - h1);
        g_yhi[o1] = packh(h2, h3);
        g_ylo[o1] = packh(v2 - h2, v3 - h3);
    }
}

// ---------------- launch ----------------
extern "C" void kernel_launch(void* const* d_in, const int* in_sizes, int n_in,
                              void* d_out, int out_size)
{
    const float* x     = (const float*)d_in[0];
    const float* w_qkv = (const float*)d_in[1];
    const float* w_o   = (const float*)d_in[2];
    const int*   amask = (const int*)d_in[3];
    float* out = (float*)d_out;

    uint32_t *xhi, *xlo, *wqh, *woh, *yhi, *ylo;
    cudaGetSymbolAddress((void**)&xhi, g_xhi);
    cudaGetSymbolAddress((void**)&xlo, g_xlo);
    cudaGetSymbolAddress((void**)&wqh, g_wqh);
    cudaGetSymbolAddress((void**)&woh, g_woh);
    cudaGetSymbolAddress((void**)&yhi, g_yhi);
    cudaGetSymbolAddress((void**)&ylo, g_ylo);

    const int smem_gemm = SMEM_GEMM_U32 * 4;
    cudaFuncSetAttribute(qkv_gemm_rope_kernel,
                         cudaFuncAttributeMaxDynamicSharedMemorySize, smem_gemm);
    cudaFuncSetAttribute(f16_gemm_kernel,
                         cudaFuncAttributeMaxDynamicSharedMemorySize, smem_gemm);
    const int smem_attn = SMEM_ATTN_U32 * 4;
    cudaFuncSetAttribute(attn_tc_kernel,
                         cudaFuncAttributeMaxDynamicSharedMemorySize, smem_attn);

    rope_table_kernel<<<256, 256>>>();

    split2_kernel<<<(B_*S_*D_/2 + 255) / 256, 256>>>(x, xhi, xlo, B_*S_*D_/2);
    wsplit_t_kernel<<<dim3(3*D_/32, D_/32), 256>>>(w_qkv, wqh, D_, 3*D_);
    wsplit_t_kernel<<<dim3(D_/32, D_/32), 256>>>(w_o, woh, D_, D_);

    // QKV = x @ w_qkv with fused RoPE + split epilogue
    qkv_gemm_rope_kernel<<<dim3(3*D_/128, B_*S_/128), 256, smem_gemm>>>(xhi, xlo, wqh);

    attn_tc_kernel<<<(S_/128) * B_ * H_, 256, smem_attn>>>(amask);

    // out = y @ w_o
    f16_gemm_kernel<<<dim3(D_/128, B_*S_/128), 256, smem_gemm>>>(
        yhi, ylo, woh, out, B_*S_, D_, D_);
}

// round 11
// speedup vs baseline: 1.0050x; 1.0050x over previous
#include <cuda_runtime.h>
#include <cuda_fp16.h>
#include <math.h>
#include <stdint.h>

#define B_  2
#define S_  2048
#define D_  1024
#define H_  16
#define HD  64

// ---------------- scratch (device globals) ----------------
__device__ float g_cos[S_*32];
__device__ float g_sin[S_*32];
// fp16 packed pairs-along-K as uint32. A-side: hi+lo. B-side: hi only.
__device__ uint32_t g_xhi[B_*S_*D_/2],  g_xlo[B_*S_*D_/2];
__device__ uint32_t g_wqh[3*D_*D_/2];                       // transposed [N][K]
__device__ uint32_t g_woh[D_*D_/2];                         // transposed [N][K]
__device__ uint32_t g_qhi[B_*H_*S_*HD/2], g_qlo[B_*H_*S_*HD/2];
__device__ uint32_t g_khi[B_*H_*S_*HD/2];
__device__ uint32_t g_vhi[B_*H_*S_*HD/2];                   // V in K-layout [s][d]
__device__ uint32_t g_yhi[B_*S_*D_/2],  g_ylo[B_*S_*D_/2];

// ---------------- helpers ----------------
__device__ __forceinline__ float hhi(float v) {
    return __half2float(__float2half_rn(v));
}
__device__ __forceinline__ uint32_t packh(float f_low, float f_high) {
    uint32_t r;
    asm("cvt.rn.f16x2.f32 %0, %1, %2;" : "=r"(r) : "f"(f_high), "f"(f_low));
    return r;
}
__device__ __forceinline__ float fexp2(float x) {
    float r;
    asm("ex2.approx.f32 %0, %1;" : "=f"(r) : "f"(x));
    return r;
}
__device__ __forceinline__ void cp16(void* dst, const void* src) {
    uint32_t d = (uint32_t)__cvta_generic_to_shared(dst);
    asm volatile("cp.async.cg.shared.global [%0], [%1], 16;\n" :: "r"(d), "l"(src));
}
__device__ __forceinline__ void cp_commit() {
    asm volatile("cp.async.commit_group;\n");
}
template<int N> __device__ __forceinline__ void cp_wait() {
    asm volatile("cp.async.wait_group %0;\n" :: "n"(N));
}
__device__ __forceinline__ void mma_f16(float* d, const uint32_t* a, const uint32_t* b) {
    asm volatile(
        "mma.sync.aligned.m16n8k16.row.col.f32.f16.f16.f32 "
        "{%0,%1,%2,%3}, {%4,%5,%6,%7}, {%8,%9}, {%0,%1,%2,%3};\n"
        : "+f"(d[0]), "+f"(d[1]), "+f"(d[2]), "+f"(d[3])
        : "r"(a[0]), "r"(a[1]), "r"(a[2]), "r"(a[3]), "r"(b[0]), "r"(b[1]));
}
__device__ __forceinline__ void ldsm4(uint32_t* r, uint32_t saddr) {
    asm volatile("ldmatrix.sync.aligned.m8n8.x4.shared.b16 {%0,%1,%2,%3}, [%4];"
        : "=r"(r[0]), "=r"(r[1]), "=r"(r[2]), "=r"(r[3]) : "r"(saddr));
}
__device__ __forceinline__ void ldsm4t(uint32_t* r, uint32_t saddr) {
    asm volatile("ldmatrix.sync.aligned.m8n8.x4.trans.shared.b16 {%0,%1,%2,%3}, [%4];"
        : "=r"(r[0]), "=r"(r[1]), "=r"(r[2]), "=r"(r[3]) : "r"(saddr));
}

#define QSC_ (0.125f * 1.44269504088896340736f)   // 1/sqrt(64) * log2(e)

// ---------------- RoPE table ----------------
__global__ void rope_table_kernel() {
    int idx = blockIdx.x * 256 + threadIdx.x;
    if (idx >= S_ * 32) return;
    int s = idx >> 5;
    int j = idx & 31;
    double inv = pow(10000.0, -((double)(2 * j)) / 64.0);
    double ang = (double)s * inv;
    g_cos[idx] = (float)cos(ang);
    g_sin[idx] = (float)sin(ang);
}

// ---------------- elementwise fp16 hi/lo split (packed pairs) ----------------
__global__ __launch_bounds__(256) void split2_kernel(
    const float* __restrict__ src, uint32_t* __restrict__ hi, uint32_t* __restrict__ lo, int n2)
{
    int i = blockIdx.x * 256 + threadIdx.x;
    if (i >= n2) return;
    float2 v = ((const float2*)src)[i];
    float h0 = hhi(v.x), h1 = hhi(v.y);
    hi[i] = packh(h0, h1);
    lo[i] = packh(v.x - h0, v.y - h1);
}

// ---------------- weight transpose + fp16 quantize: w[K][N] -> wt[N][K] ----------------
__global__ __launch_bounds__(256) void wsplit_t_kernel(
    const float* __restrict__ w, uint32_t* __restrict__ th, int Kd, int Nd)
{
    __shared__ float tile[32][33];
    int n0 = blockIdx.x * 32, k0 = blockIdx.y * 32;
    int tx = threadIdx.x & 31, ty = threadIdx.x >> 5;
    #pragma unroll
    for (int r = 0; r < 32; r += 8)
        tile[ty + r][tx] = w[(size_t)(k0 + ty + r) * Nd + n0 + tx];
    __syncthreads();
    __half* thb = (__half*)th;
    #pragma unroll
    for (int r = 0; r < 32; r += 8) {
        int n = n0 + ty + r, k = k0 + tx;
        thb[(size_t)n * Kd + k] = __float2half_rn(tile[tx][ty + r]);
    }
}

// ---------------- shared GEMM plumbing ----------------
#define KS 20
#define G_AH 0
#define G_AL 2560
#define G_BH 5120
#define G_STAGE 7680
#define SMEM_GEMM_U32 (3*G_STAGE)

__device__ __forceinline__ void gemm_stage_load(
    uint32_t* st, const uint32_t* Ah, const uint32_t* Al, const uint32_t* Bh,
    int kp0, int tid, int Kp)
{
    const int row = tid >> 1;
    const int c = (tid & 1) * 8;
    const size_t ga = (size_t)row * Kp + kp0 + c;
    cp16(&st[G_AH + row * KS + c],     Ah + ga);
    cp16(&st[G_AH + row * KS + c + 4], Ah + ga + 4);
    cp16(&st[G_AL + row * KS + c],     Al + ga);
    cp16(&st[G_AL + row * KS + c + 4], Al + ga + 4);
    cp16(&st[G_BH + row * KS + c],     Bh + ga);
    cp16(&st[G_BH + row * KS + c + 4], Bh + ga + 4);
}

// mainloop: hi-pass then lo-pass so dependent-acc MMAs sit >= 16 apart
#define GEMM_MAINLOOP(ACC)                                                              \
    const int NT = Kp / 16;                                                             \
    gemm_stage_load(smg, Ahi, Alo, Bhi, 0, tid, Kp);                                    \
    cp_commit();                                                                        \
    gemm_stage_load(smg + G_STAGE, Ahi, Alo, Bhi, 16, tid, Kp);                         \
    cp_commit();                                                                        \
    int stage = 0;                                                                      \
    for (int it = 0; it < NT; it++) {                                                   \
        cp_wait<1>();                                                                   \
        __syncthreads();                                                                \
        if (it + 2 < NT) {                                                              \
            int s2 = stage + 2; if (s2 >= 3) s2 -= 3;                                   \
            gemm_stage_load(smg + s2 * G_STAGE, Ahi, Alo, Bhi, (it + 2) * 16, tid, Kp); \
        }                                                                               \
        cp_commit();                                                                    \
        const uint32_t stB = smB + (stage * G_STAGE) * 4;                               \
        _Pragma("unroll")                                                               \
        for (int kstep = 0; kstep < 2; kstep++) {                                       \
            const int k8 = kstep * 8;                                                   \
            uint32_t ah[2][4], al[2][4];                                                \
            _Pragma("unroll")                                                           \
            for (int mt = 0; mt < 2; mt++) {                                            \
                const uint32_t ab = stB + ((G_AH + (mBase + mt*16 + aR)*KS + k8 + aC) << 2); \
                ldsm4(ah[mt], ab);                                                      \
                ldsm4(al[mt], ab + (G_AL - G_AH) * 4);                                  \
            }                                                                           \
            uint32_t bb[4][4];                                                          \
            _Pragma("unroll")                                                           \
            for (int ntp = 0; ntp < 4; ntp++)                                           \
                ldsm4(bb[ntp], stB + ((G_BH + (nBase + ntp*16 + bR)*KS + k8 + bC) << 2)); \
            _Pragma("unroll")                                                           \
            for (int ntp = 0; ntp < 4; ntp++)                                           \
                _Pragma("unroll")                                                       \
                for (int mt = 0; mt < 2; mt++) {                                        \
                    mma_f16(ACC[mt][2*ntp],     ah[mt], bb[ntp]);                       \
                    mma_f16(ACC[mt][2*ntp + 1], ah[mt], bb[ntp] + 2);                   \
                }                                                                       \
            _Pragma("unroll")                                                           \
            for (int ntp = 0; ntp < 4; ntp++)                                           \
                _Pragma("unroll")                                                       \
                for (int mt = 0; mt < 2; mt++) {                                        \
                    mma_f16(ACC[mt][2*ntp],     al[mt], bb[ntp]);                       \
                    mma_f16(ACC[mt][2*ntp + 1], al[mt], bb[ntp] + 2);                   \
                }                                                                       \
        }                                                                               \
        if (++stage == 3) stage = 0;                                                    \
    }

// ---------------- QKV GEMM with fused RoPE + fp16 split epilogue ----------------
__global__ __launch_bounds__(256, 2) void qkv_gemm_rope_kernel(
    const uint32_t* __restrict__ Ahi, const uint32_t* __restrict__ Alo,
    const uint32_t* __restrict__ Bhi)
{
    extern __shared__ uint32_t smg[];
    const int Kp = D_ >> 1;
    const int tid  = threadIdx.x;
    const int warp = tid >> 5;
    const int lane = tid & 31;
    const int g = lane >> 2;
    const int t = lane & 3;
    const int mBase = (warp >> 1) * 32;
    const int nBase = (warp & 1) * 64;

    const int r8 = lane & 7;
    const int aR = ((lane >> 3) & 1) * 8 + r8;
    const int aC = ((lane >> 4) & 1) * 4;
    const int bR = ((lane >> 4) & 1) * 8 + r8;
    const int bC = ((lane >> 3) & 1) * 4;
    const uint32_t smB = (uint32_t)__cvta_generic_to_shared(smg);

    Ahi += (size_t)blockIdx.y * 128 * Kp;
    Alo += (size_t)blockIdx.y * 128 * Kp;
    Bhi += (size_t)blockIdx.x * 128 * Kp;

    float acc[2][8][4];
    #pragma unroll
    for (int mt = 0; mt < 2; mt++)
        #pragma unroll
        for (int nt = 0; nt < 8; nt++)
            #pragma unroll
            for (int r = 0; r < 4; r++) acc[mt][nt][r] = 0.f;

    GEMM_MAINLOOP(acc)

    // ---- fused epilogue: RoPE (q,k) + fp16 split, V passthrough quantize ----
    const int gcolbase = blockIdx.x * 128 + nBase;   // multiple of 64
    const int region = gcolbase >> 10;               // 0=q 1=k 2=v
    const int head   = (gcolbase & 1023) >> 6;

    #pragma unroll
    for (int mt = 0; mt < 2; mt++) {
        #pragma unroll
        for (int rs = 0; rs < 2; rs++) {
            const int m = blockIdx.y * 128 + mBase + mt * 16 + g + rs * 8;
            const int b = m >> 11, s = m & 2047;
            const size_t dbase = ((size_t)(b * 16 + head) * S_ + s) * 32;
            if (region == 2) {
                #pragma unroll
                for (int nt = 0; nt < 8; nt++) {
                    float v0 = acc[mt][nt][rs * 2 + 0];
                    float v1 = acc[mt][nt][rs * 2 + 1];
                    g_vhi[dbase + nt * 4 + t] = packh(hhi(v0), hhi(v1));
                }
            } else {
                #pragma unroll
                for (int nt = 0; nt < 8; nt++) {
                    const int i0 = nt * 8 + t * 2;
                    const int j0 = i0 & 31;
                    float c0 = g_cos[s * 32 + j0], c1 = g_cos[s * 32 + j0 + 1];
                    float s0 = g_sin[s * 32 + j0], s1 = g_sin[s * 32 + j0 + 1];
                    float sg = (i0 < 32) ? -1.f : 1.f;
                    float v0 = acc[mt][nt][rs * 2 + 0];
                    float v1 = acc[mt][nt][rs * 2 + 1];
                    float p0 = acc[mt][nt ^ 4][rs * 2 + 0];
                    float p1 = acc[mt][nt ^ 4][rs * 2 + 1];
                    float r0 = v0 * c0 + sg * p0 * s0;
                    float r1 = v1 * c1 + sg * p1 * s1;
                    if (region == 0) {
                        r0 *= QSC_; r1 *= QSC_;
                        float h0 = hhi(r0), h1 = hhi(r1);
                        g_qhi[dbase + nt * 4 + t] = packh(h0, h1);
                        g_qlo[dbase + nt * 4 + t] = packh(r0 - h0, r1 - h1);
                    } else {
                        g_khi[dbase + nt * 4 + t] = packh(hhi(r0), hhi(r1));
                    }
                }
            }
        }
    }
}

// ---------------- generic fp16 2-product GEMM (O-proj) ----------------
__global__ __launch_bounds__(256, 2) void f16_gemm_kernel(
    const uint32_t* __restrict__ Ahi, const uint32_t* __restrict__ Alo,
    const uint32_t* __restrict__ Bhi,
    float* __restrict__ C, int M, int N, int K)
{
    extern __shared__ uint32_t smg[];
    const int Kp = K >> 1;
    const int tid  = threadIdx.x;
    const int warp = tid >> 5;
    const int lane = tid & 31;
    const int g = lane >> 2;
    const int t = lane & 3;
    const int mBase = (warp >> 1) * 32;
    const int nBase = (warp & 1) * 64;

    const int r8 = lane & 7;
    const int aR = ((lane >> 3) & 1) * 8 + r8;
    const int aC = ((lane >> 4) & 1) * 4;
    const int bR = ((lane >> 4) & 1) * 8 + r8;
    const int bC = ((lane >> 3) & 1) * 4;
    const uint32_t smB = (uint32_t)__cvta_generic_to_shared(smg);

    Ahi += (size_t)blockIdx.y * 128 * Kp;
    Alo += (size_t)blockIdx.y * 128 * Kp;
    Bhi += (size_t)blockIdx.x * 128 * Kp;

    float acc[2][8][4];
    #pragma unroll
    for (int mt = 0; mt < 2; mt++)
        #pragma unroll
        for (int nt = 0; nt < 8; nt++)
            #pragma unroll
            for (int r = 0; r < 4; r++) acc[mt][nt][r] = 0.f;

    GEMM_MAINLOOP(acc)

    C += (size_t)blockIdx.y * 128 * N + blockIdx.x * 128;
    #pragma unroll
    for (int mt = 0; mt < 2; mt++) {
        const int r0 = mBase + mt * 16 + g;
        #pragma unroll
        for (int nt = 0; nt < 8; nt++) {
            const int c = nBase + nt * 8 + t * 2;
            *(float2*)&C[(size_t)r0 * N + c]       = make_float2(acc[mt][nt][0], acc[mt][nt][1]);
            *(float2*)&C[(size_t)(r0 + 8) * N + c] = make_float2(acc[mt][nt][2], acc[mt][nt][3]);
        }
    }
}

// ---------------- fp16 tensor-core causal flash attention ----------------
#define APS 36
#define A_PH 0
#define A_PL 4608
#define A_KV 9216
#define KV_KH 0
#define KV_VH 2304
#define KV_STAGE 4608
#define A_MSK (A_KV + 2*KV_STAGE)
#define SMEM_ATTN_U32 (A_MSK + S_)

__device__ __forceinline__ void attn_stage_load(
    uint32_t* sma, int st, const uint32_t* kh, const uint32_t* vh, int kt, int tid)
{
    uint32_t* base = sma + A_KV + st * KV_STAGE;
    const int r = tid >> 2, c = tid & 3;
    const size_t gk = (size_t)(kt * 64 + r) * 32;
    cp16(&base[KV_KH + r * APS + c * 4],       kh + gk + c * 4);
    cp16(&base[KV_KH + r * APS + (c + 4) * 4], kh + gk + (c + 4) * 4);
    cp16(&base[KV_VH + r * APS + c * 4],       vh + gk + c * 4);
    cp16(&base[KV_VH + r * APS + (c + 4) * 4], vh + gk + (c + 4) * 4);
}

__global__ __launch_bounds__(256, 2) void attn_tc_kernel(const int* __restrict__ amask) {
    extern __shared__ uint32_t sma[];
    uint32_t* sPh = sma + A_PH;
    uint32_t* sPl = sma + A_PL;
    float* sMf = (float*)(sma + A_MSK);

    const int tid  = threadIdx.x;
    const int warp = tid >> 5;
    const int lane = tid & 31;
    const int g = lane >> 2;
    const int t = lane & 3;
    // LPT ordering: heaviest q-tiles first
    const int qtile = (S_ / 128 - 1) - (int)(blockIdx.x >> 5);
    const int bh    = blockIdx.x & 31;
    const int b  = bh >> 4;
    const int h  = bh & 15;
    const int qbase = qtile * 128;
    const int wrow  = warp * 16;

    const int r8 = lane & 7;
    const int aR = ((lane >> 3) & 1) * 8 + r8;
    const int aC = ((lane >> 4) & 1) * 4;
    const int bR = ((lane >> 4) & 1) * 8 + r8;
    const int bC = ((lane >> 3) & 1) * 4;
    const int vR = ((lane >> 3) & 1) * 8 + r8;
    const int vC = ((lane >> 4) & 1) * 4;
    const uint32_t smB = (uint32_t)__cvta_generic_to_shared(sma);

    const uint32_t* kh = g_khi + (size_t)bh * S_ * 32;
    const uint32_t* vh = g_vhi + (size_t)bh * S_ * 32;

    const int nkt = (qbase + 128) / 64;

    attn_stage_load(sma, 0, kh, vh, 0, tid);
    cp_commit();

    {
        const uint32_t* qgh = g_qhi + ((size_t)bh * S_ + qbase) * 32;
        const uint32_t* qgl = g_qlo + ((size_t)bh * S_ + qbase) * 32;
        for (int idx = tid; idx < 1024; idx += 256) {
            int r = idx >> 3, c4 = (idx & 7) * 4;
            *(uint4*)&sPh[r * APS + c4] = *(const uint4*)(qgh + r * 32 + c4);
            *(uint4*)&sPl[r * APS + c4] = *(const uint4*)(qgl + r * 32 + c4);
        }
        for (int idx = tid; idx < S_; idx += 256)
            sMf[idx] = (amask[b * S_ + idx] == 0) ? -INFINITY : 0.f;
    }
    __syncthreads();

    uint32_t Qh[4][4], Ql[4][4];
    #pragma unroll
    for (int ks = 0; ks < 4; ks++) {
        const uint32_t qaddr = smB + (((wrow + aR) * APS + ks * 8 + aC) << 2);
        ldsm4(Qh[ks], qaddr);
        ldsm4(Ql[ks], qaddr + A_PL * 4);
    }
    // each warp reads/writes only its own 16 sP rows from here on

    float oacc[8][4];
    #pragma unroll
    for (int nt = 0; nt < 8; nt++)
        #pragma unroll
        for (int r = 0; r < 4; r++) oacc[nt][r] = 0.f;
    float mrun[2] = {-INFINITY, -INFINITY};
    float lrun[2] = {0.f, 0.f};

    for (int kt = 0; kt < nkt; kt++) {
        if (kt + 1 < nkt) {
            attn_stage_load(sma, (kt + 1) & 1, kh, vh, kt + 1, tid);
            cp_commit();
            cp_wait<1>();
        } else {
            cp_wait<0>();
        }
        __syncthreads();

        if (kt * 64 <= qbase + wrow + 15) {
            const uint32_t kvB = smB + ((A_KV + (kt & 1) * KV_STAGE) << 2);

            // ---- S = Q K^T  (hi pass per ks, then lo pass; dependent dist >= 8) ----
            float sacc[8][4];
            #pragma unroll
            for (int nt = 0; nt < 8; nt++)
                #pragma unroll
                for (int r = 0; r < 4; r++) sacc[nt][r] = 0.f;

            #pragma unroll
            for (int ks = 0; ks < 4; ks++) {
                uint32_t bb[4][4];
                #pragma unroll
                for (int ntp = 0; ntp < 4; ntp++)
                    ldsm4(bb[ntp], kvB + ((KV_KH + (ntp * 16 + bR) * APS + ks * 8 + bC) << 2));
                #pragma unroll
                for (int ntp = 0; ntp < 4; ntp++) {
                    mma_f16(sacc[2 * ntp],     Qh[ks], bb[ntp]);
                    mma_f16(sacc[2 * ntp + 1], Qh[ks], bb[ntp] + 2);
                }
                #pragma unroll
                for (int ntp = 0; ntp < 4; ntp++) {
                    mma_f16(sacc[2 * ntp],     Ql[ks], bb[ntp]);
                    mma_f16(sacc[2 * ntp + 1], Ql[ks], bb[ntp] + 2);
                }
            }

            // ---- masks + row max (log2 domain) ----
            const bool diag = (kt * 64 + 63) > (qbase + wrow);
            float tmax[2] = {-INFINITY, -INFINITY};
            #pragma unroll
            for (int nt = 0; nt < 8; nt++) {
                #pragma unroll
                for (int e = 0; e < 4; e++) {
                    const int colL = nt * 8 + t * 2 + (e & 1);
                    float v = sacc[nt][e] + sMf[kt * 64 + colL];
                    if (diag) {
                        const int row = qbase + wrow + g + ((e >> 1) << 3);
                        const int col = kt * 64 + colL;
                        if (col > row) v = -INFINITY;
                    }
                    sacc[nt][e] = v;
                    tmax[e >> 1] = fmaxf(tmax[e >> 1], v);
                }
            }
            #pragma unroll
            for (int i = 0; i < 2; i++) {
                tmax[i] = fmaxf(tmax[i], __shfl_xor_sync(0xffffffff, tmax[i], 1));
                tmax[i] = fmaxf(tmax[i], __shfl_xor_sync(0xffffffff, tmax[i], 2));
            }

            // ---- online softmax (base-2) ----
            float corr[2], psum[2] = {0.f, 0.f};
            #pragma unroll
            for (int i = 0; i < 2; i++) {
                float mnew = fmaxf(mrun[i], tmax[i]);
                corr[i] = fexp2(mrun[i] - mnew);
                mrun[i] = mnew;
                lrun[i] *= corr[i];
            }
            #pragma unroll
            for (int nt = 0; nt < 8; nt++) {
                oacc[nt][0] *= corr[0]; oacc[nt][1] *= corr[0];
                oacc[nt][2] *= corr[1]; oacc[nt][3] *= corr[1];
            }
            #pragma unroll
            for (int nt = 0; nt < 8; nt++) {
                #pragma unroll
                for (int half = 0; half < 2; half++) {
                    float p0 = fexp2(sacc[nt][half * 2 + 0] - mrun[half]);
                    float p1 = fexp2(sacc[nt][half * 2 + 1] - mrun[half]);
                    psum[half] += p0 + p1;
                    float h0 = hhi(p0), h1 = hhi(p1);
                    const int row = wrow + g + half * 8;
                    sPh[row * APS + nt * 4 + t] = packh(h0, h1);
                    sPl[row * APS + nt * 4 + t] = packh(p0 - h0, p1 - h1);
                }
            }
            #pragma unroll
            for (int i = 0; i < 2; i++) {
                psum[i] += __shfl_xor_sync(0xffffffff, psum[i], 1);
                psum[i] += __shfl_xor_sync(0xffffffff, psum[i], 2);
                lrun[i] += psum[i];
            }
            __syncwarp();

            // ---- O += P V  (V in [k][n] layout, trans frags; hi pass then lo pass) ----
            #pragma unroll
            for (int ks = 0; ks < 4; ks++) {
                uint32_t ph4[4], pl4[4];
                const uint32_t paddr = smB + (((wrow + aR) * APS + ks * 8 + aC) << 2);
                ldsm4(ph4, paddr);
                ldsm4(pl4, paddr + A_PL * 4);
                uint32_t vv[4][4];
                #pragma unroll
                for (int ntp = 0; ntp < 4; ntp++)
                    ldsm4t(vv[ntp], kvB + ((KV_VH + (ks * 16 + vR) * APS + ntp * 8 + vC) << 2));
                #pragma unroll
                for (int ntp = 0; ntp < 4; ntp++) {
                    mma_f16(oacc[2 * ntp],     ph4, vv[ntp]);
                    mma_f16(oacc[2 * ntp + 1], ph4, vv[ntp] + 2);
                }
                #pragma unroll
                for (int ntp = 0; ntp < 4; ntp++) {
                    mma_f16(oacc[2 * ntp],     pl4, vv[ntp]);
                    mma_f16(oacc[2 * ntp + 1], pl4, vv[ntp] + 2);
                }
            }
            __syncwarp();
        }
        __syncthreads();
    }

    // ---- epilogue: o/l, fp16 split, packed write ----
    const float inv0 = 1.f / lrun[0];
    const float inv1 = 1.f / lrun[1];
    const int r0 = qbase + wrow + g;
    const int r1 = r0 + 8;
    #pragma unroll
    for (int nt = 0; nt < 8; nt++) {
        float v0 = oacc[nt][0] * inv0, v1 = oacc[nt][1] * inv0;
        float v2 = oacc[nt][2] * inv1, v3 = oacc[nt][3] * inv1;
        const size_t o0 = (size_t)(b * S_ + r0) * 512 + h * 32 + nt * 4 + t;
        const size_t o1 = (size_t)(b * S_ + r1) * 512 + h * 32 + nt * 4 + t;
        float h0 = hhi(v0), h1 = hhi(v1), h2 = hhi(v2), h3 = hhi(v3);
        g_yhi[o0] = packh(h0, h1);
        g_ylo[o0] = packh(v0 - h0, v1 - h1);
        g_yhi[o1] = packh(h2, h3);
        g_ylo[o1] = packh(v2 - h2, v3 - h3);
    }
}

// ---------------- launch ----------------
extern "C" void kernel_launch(void* const* d_in, const int* in_sizes, int n_in,
                              void* d_out, int out_size)
{
    const float* x     = (const float*)d_in[0];
    const float* w_qkv = (const float*)d_in[1];
    const float* w_o   = (const float*)d_in[2];
    const int*   amask = (const int*)d_in[3];
    float* out = (float*)d_out;

    uint32_t *xhi, *xlo, *wqh, *woh, *yhi, *ylo;
    cudaGetSymbolAddress((void**)&xhi, g_xhi);
    cudaGetSymbolAddress((void**)&xlo, g_xlo);
    cudaGetSymbolAddress((void**)&wqh, g_wqh);
    cudaGetSymbolAddress((void**)&woh, g_woh);
    cudaGetSymbolAddress((void**)&yhi, g_yhi);
    cudaGetSymbolAddress((void**)&ylo, g_ylo);

    const int smem_gemm = SMEM_GEMM_U32 * 4;
    cudaFuncSetAttribute(qkv_gemm_rope_kernel,
                         cudaFuncAttributeMaxDynamicSharedMemorySize, smem_gemm);
    cudaFuncSetAttribute(f16_gemm_kernel,
                         cudaFuncAttributeMaxDynamicSharedMemorySize, smem_gemm);
    const int smem_attn = SMEM_ATTN_U32 * 4;
    cudaFuncSetAttribute(attn_tc_kernel,
                         cudaFuncAttributeMaxDynamicSharedMemorySize, smem_attn);

    rope_table_kernel<<<256, 256>>>();

    split2_kernel<<<(B_*S_*D_/2 + 255) / 256, 256>>>(x, xhi, xlo, B_*S_*D_/2);
    wsplit_t_kernel<<<dim3(3*D_/32, D_/32), 256>>>(w_qkv, wqh, D_, 3*D_);
    wsplit_t_kernel<<<dim3(D_/32, D_/32), 256>>>(w_o, woh, D_, D_);

    // QKV = x @ w_qkv with fused RoPE + split epilogue
    qkv_gemm_rope_kernel<<<dim3(3*D_/128, B_*S_/128), 256, smem_gemm>>>(xhi, xlo, wqh);

    attn_tc_kernel<<<(S_/128) * B_ * H_, 256, smem_attn>>>(amask);

    // out = y @ w_o
    f16_gemm_kernel<<<dim3(D_/128, B_*S_/128), 256, smem_gemm>>>(
        yhi, ylo, woh, out, B_*S_, D_, D_);
}

// round 12
// speedup vs baseline: 1.0187x; 1.0137x over previous
#include <cuda_runtime.h>
#include <cuda_fp16.h>
#include <math.h>
#include <stdint.h>

#define B_  2
#define S_  2048
#define D_  1024
#define H_  16
#define HD  64

// ---------------- scratch (device globals) ----------------
__device__ float g_cos[S_*32];
__device__ float g_sin[S_*32];
// fp16 packed pairs-along-K as uint32. A-side: hi+lo. B-side: hi only.
__device__ uint32_t g_xhi[B_*S_*D_/2],  g_xlo[B_*S_*D_/2];
__device__ uint32_t g_wqh[3*D_*D_/2];                       // transposed [N][K]
__device__ uint32_t g_woh[D_*D_/2];                         // transposed [N][K]
__device__ uint32_t g_qhi[B_*H_*S_*HD/2], g_qlo[B_*H_*S_*HD/2];
__device__ uint32_t g_khi[B_*H_*S_*HD/2];
__device__ uint32_t g_vhi[B_*H_*S_*HD/2];                   // V in K-layout [s][d]
__device__ uint32_t g_yhi[B_*S_*D_/2],  g_ylo[B_*S_*D_/2];

// ---------------- helpers ----------------
__device__ __forceinline__ float hhi(float v) {
    return __half2float(__float2half_rn(v));
}
__device__ __forceinline__ uint32_t packh(float f_low, float f_high) {
    uint32_t r;
    asm("cvt.rn.f16x2.f32 %0, %1, %2;" : "=r"(r) : "f"(f_high), "f"(f_low));
    return r;
}
__device__ __forceinline__ float fexp2(float x) {
    float r;
    asm("ex2.approx.f32 %0, %1;" : "=f"(r) : "f"(x));
    return r;
}
__device__ __forceinline__ void cp16(void* dst, const void* src) {
    uint32_t d = (uint32_t)__cvta_generic_to_shared(dst);
    asm volatile("cp.async.cg.shared.global [%0], [%1], 16;\n" :: "r"(d), "l"(src));
}
__device__ __forceinline__ void cp_commit() {
    asm volatile("cp.async.commit_group;\n");
}
template<int N> __device__ __forceinline__ void cp_wait() {
    asm volatile("cp.async.wait_group %0;\n" :: "n"(N));
}
__device__ __forceinline__ void mma_f16(float* d, const uint32_t* a, const uint32_t* b) {
    asm volatile(
        "mma.sync.aligned.m16n8k16.row.col.f32.f16.f16.f32 "
        "{%0,%1,%2,%3}, {%4,%5,%6,%7}, {%8,%9}, {%0,%1,%2,%3};\n"
        : "+f"(d[0]), "+f"(d[1]), "+f"(d[2]), "+f"(d[3])
        : "r"(a[0]), "r"(a[1]), "r"(a[2]), "r"(a[3]), "r"(b[0]), "r"(b[1]));
}
__device__ __forceinline__ void ldsm4(uint32_t* r, uint32_t saddr) {
    asm volatile("ldmatrix.sync.aligned.m8n8.x4.shared.b16 {%0,%1,%2,%3}, [%4];"
        : "=r"(r[0]), "=r"(r[1]), "=r"(r[2]), "=r"(r[3]) : "r"(saddr));
}
__device__ __forceinline__ void ldsm4t(uint32_t* r, uint32_t saddr) {
    asm volatile("ldmatrix.sync.aligned.m8n8.x4.trans.shared.b16 {%0,%1,%2,%3}, [%4];"
        : "=r"(r[0]), "=r"(r[1]), "=r"(r[2]), "=r"(r[3]) : "r"(saddr));
}

#define QSC_ (0.125f * 1.44269504088896340736f)   // 1/sqrt(64) * log2(e)

// ---------------- RoPE table ----------------
__global__ void rope_table_kernel() {
    int idx = blockIdx.x * 256 + threadIdx.x;
    if (idx >= S_ * 32) return;
    int s = idx >> 5;
    int j = idx & 31;
    double inv = pow(10000.0, -((double)(2 * j)) / 64.0);
    double ang = (double)s * inv;
    g_cos[idx] = (float)cos(ang);
    g_sin[idx] = (float)sin(ang);
}

// ---------------- elementwise fp16 hi/lo split (packed pairs) ----------------
__global__ __launch_bounds__(256) void split2_kernel(
    const float* __restrict__ src, uint32_t* __restrict__ hi, uint32_t* __restrict__ lo, int n2)
{
    int i = blockIdx.x * 256 + threadIdx.x;
    if (i >= n2) return;
    float2 v = ((const float2*)src)[i];
    float h0 = hhi(v.x), h1 = hhi(v.y);
    hi[i] = packh(h0, h1);
    lo[i] = packh(v.x - h0, v.y - h1);
}

// ---------------- weight transpose + fp16 quantize: w[K][N] -> wt[N][K] ----------------
__global__ __launch_bounds__(256) void wsplit_t_kernel(
    const float* __restrict__ w, uint32_t* __restrict__ th, int Kd, int Nd)
{
    __shared__ float tile[32][33];
    int n0 = blockIdx.x * 32, k0 = blockIdx.y * 32;
    int tx = threadIdx.x & 31, ty = threadIdx.x >> 5;
    #pragma unroll
    for (int r = 0; r < 32; r += 8)
        tile[ty + r][tx] = w[(size_t)(k0 + ty + r) * Nd + n0 + tx];
    __syncthreads();
    __half* thb = (__half*)th;
    #pragma unroll
    for (int r = 0; r < 32; r += 8) {
        int n = n0 + ty + r, k = k0 + tx;
        thb[(size_t)n * Kd + k] = __float2half_rn(tile[tx][ty + r]);
    }
}

// ---------------- shared GEMM plumbing ----------------
#define KS 20
#define G_AH 0
#define G_AL 2560
#define G_BH 5120
#define G_STAGE 7680
#define SMEM_GEMM_U32 (3*G_STAGE)

__device__ __forceinline__ void gemm_stage_load(
    uint32_t* st, const uint32_t* Ah, const uint32_t* Al, const uint32_t* Bh,
    int kp0, int tid, int Kp)
{
    const int row = tid >> 1;
    const int c = (tid & 1) * 8;
    const size_t ga = (size_t)row * Kp + kp0 + c;
    cp16(&st[G_AH + row * KS + c],     Ah + ga);
    cp16(&st[G_AH + row * KS + c + 4], Ah + ga + 4);
    cp16(&st[G_AL + row * KS + c],     Al + ga);
    cp16(&st[G_AL + row * KS + c + 4], Al + ga + 4);
    cp16(&st[G_BH + row * KS + c],     Bh + ga);
    cp16(&st[G_BH + row * KS + c + 4], Bh + ga + 4);
}

// mainloop: hi-pass then lo-pass so dependent-acc MMAs sit far apart
#define GEMM_MAINLOOP(ACC)                                                              \
    const int NT = Kp / 16;                                                             \
    gemm_stage_load(smg, Ahi, Alo, Bhi, 0, tid, Kp);                                    \
    cp_commit();                                                                        \
    gemm_stage_load(smg + G_STAGE, Ahi, Alo, Bhi, 16, tid, Kp);                         \
    cp_commit();                                                                        \
    int stage = 0;                                                                      \
    for (int it = 0; it < NT; it++) {                                                   \
        cp_wait<1>();                                                                   \
        __syncthreads();                                                                \
        if (it + 2 < NT) {                                                              \
            int s2 = stage + 2; if (s2 >= 3) s2 -= 3;                                   \
            gemm_stage_load(smg + s2 * G_STAGE, Ahi, Alo, Bhi, (it + 2) * 16, tid, Kp); \
        }                                                                               \
        cp_commit();                                                                    \
        const uint32_t stB = smB + (stage * G_STAGE) * 4;                               \
        _Pragma("unroll")                                                               \
        for (int kstep = 0; kstep < 2; kstep++) {                                       \
            const int k8 = kstep * 8;                                                   \
            uint32_t ah[2][4], al[2][4];                                                \
            _Pragma("unroll")                                                           \
            for (int mt = 0; mt < 2; mt++) {                                            \
                const uint32_t ab = stB + ((G_AH + (mBase + mt*16 + aR)*KS + k8 + aC) << 2); \
                ldsm4(ah[mt], ab);                                                      \
                ldsm4(al[mt], ab + (G_AL - G_AH) * 4);                                  \
            }                                                                           \
            uint32_t bb[4][4];                                                          \
            _Pragma("unroll")                                                           \
            for (int ntp = 0; ntp < 4; ntp++)                                           \
                ldsm4(bb[ntp], stB + ((G_BH + (nBase + ntp*16 + bR)*KS + k8 + bC) << 2)); \
            _Pragma("unroll")                                                           \
            for (int ntp = 0; ntp < 4; ntp++)                                           \
                _Pragma("unroll")                                                       \
                for (int mt = 0; mt < 2; mt++) {                                        \
                    mma_f16(ACC[mt][2*ntp],     ah[mt], bb[ntp]);                       \
                    mma_f16(ACC[mt][2*ntp + 1], ah[mt], bb[ntp] + 2);                   \
                }                                                                       \
            _Pragma("unroll")                                                           \
            for (int ntp = 0; ntp < 4; ntp++)                                           \
                _Pragma("unroll")                                                       \
                for (int mt = 0; mt < 2; mt++) {                                        \
                    mma_f16(ACC[mt][2*ntp],     al[mt], bb[ntp]);                       \
                    mma_f16(ACC[mt][2*ntp + 1], al[mt], bb[ntp] + 2);                   \
                }                                                                       \
        }                                                                               \
        if (++stage == 3) stage = 0;                                                    \
    }

// ---------------- QKV GEMM with fused RoPE + fp16 split epilogue ----------------
__global__ __launch_bounds__(256, 2) void qkv_gemm_rope_kernel(
    const uint32_t* __restrict__ Ahi, const uint32_t* __restrict__ Alo,
    const uint32_t* __restrict__ Bhi)
{
    extern __shared__ uint32_t smg[];
    const int Kp = D_ >> 1;
    const int tid  = threadIdx.x;
    const int warp = tid >> 5;
    const int lane = tid & 31;
    const int g = lane >> 2;
    const int t = lane & 3;
    const int mBase = (warp >> 1) * 32;
    const int nBase = (warp & 1) * 64;

    const int r8 = lane & 7;
    const int aR = ((lane >> 3) & 1) * 8 + r8;
    const int aC = ((lane >> 4) & 1) * 4;
    const int bR = ((lane >> 4) & 1) * 8 + r8;
    const int bC = ((lane >> 3) & 1) * 4;
    const uint32_t smB = (uint32_t)__cvta_generic_to_shared(smg);

    Ahi += (size_t)blockIdx.y * 128 * Kp;
    Alo += (size_t)blockIdx.y * 128 * Kp;
    Bhi += (size_t)blockIdx.x * 128 * Kp;

    float acc[2][8][4];
    #pragma unroll
    for (int mt = 0; mt < 2; mt++)
        #pragma unroll
        for (int nt = 0; nt < 8; nt++)
            #pragma unroll
            for (int r = 0; r < 4; r++) acc[mt][nt][r] = 0.f;

    GEMM_MAINLOOP(acc)

    // ---- fused epilogue: RoPE (q,k) + fp16 split, V passthrough quantize ----
    const int gcolbase = blockIdx.x * 128 + nBase;   // multiple of 64
    const int region = gcolbase >> 10;               // 0=q 1=k 2=v
    const int head   = (gcolbase & 1023) >> 6;

    #pragma unroll
    for (int mt = 0; mt < 2; mt++) {
        #pragma unroll
        for (int rs = 0; rs < 2; rs++) {
            const int m = blockIdx.y * 128 + mBase + mt * 16 + g + rs * 8;
            const int b = m >> 11, s = m & 2047;
            const size_t dbase = ((size_t)(b * 16 + head) * S_ + s) * 32;
            if (region == 2) {
                #pragma unroll
                for (int nt = 0; nt < 8; nt++) {
                    float v0 = acc[mt][nt][rs * 2 + 0];
                    float v1 = acc[mt][nt][rs * 2 + 1];
                    g_vhi[dbase + nt * 4 + t] = packh(hhi(v0), hhi(v1));
                }
            } else {
                #pragma unroll
                for (int nt = 0; nt < 8; nt++) {
                    const int i0 = nt * 8 + t * 2;
                    const int j0 = i0 & 31;
                    float c0 = g_cos[s * 32 + j0], c1 = g_cos[s * 32 + j0 + 1];
                    float s0 = g_sin[s * 32 + j0], s1 = g_sin[s * 32 + j0 + 1];
                    float sg = (i0 < 32) ? -1.f : 1.f;
                    float v0 = acc[mt][nt][rs * 2 + 0];
                    float v1 = acc[mt][nt][rs * 2 + 1];
                    float p0 = acc[mt][nt ^ 4][rs * 2 + 0];
                    float p1 = acc[mt][nt ^ 4][rs * 2 + 1];
                    float r0 = v0 * c0 + sg * p0 * s0;
                    float r1 = v1 * c1 + sg * p1 * s1;
                    if (region == 0) {
                        r0 *= QSC_; r1 *= QSC_;
                        float h0 = hhi(r0), h1 = hhi(r1);
                        g_qhi[dbase + nt * 4 + t] = packh(h0, h1);
                        g_qlo[dbase + nt * 4 + t] = packh(r0 - h0, r1 - h1);
                    } else {
                        g_khi[dbase + nt * 4 + t] = packh(hhi(r0), hhi(r1));
                    }
                }
            }
        }
    }
}

// ---------------- generic fp16 2-product GEMM (O-proj) ----------------
__global__ __launch_bounds__(256, 2) void f16_gemm_kernel(
    const uint32_t* __restrict__ Ahi, const uint32_t* __restrict__ Alo,
    const uint32_t* __restrict__ Bhi,
    float* __restrict__ C, int M, int N, int K)
{
    extern __shared__ uint32_t smg[];
    const int Kp = K >> 1;
    const int tid  = threadIdx.x;
    const int warp = tid >> 5;
    const int lane = tid & 31;
    const int g = lane >> 2;
    const int t = lane & 3;
    const int mBase = (warp >> 1) * 32;
    const int nBase = (warp & 1) * 64;

    const int r8 = lane & 7;
    const int aR = ((lane >> 3) & 1) * 8 + r8;
    const int aC = ((lane >> 4) & 1) * 4;
    const int bR = ((lane >> 4) & 1) * 8 + r8;
    const int bC = ((lane >> 3) & 1) * 4;
    const uint32_t smB = (uint32_t)__cvta_generic_to_shared(smg);

    Ahi += (size_t)blockIdx.y * 128 * Kp;
    Alo += (size_t)blockIdx.y * 128 * Kp;
    Bhi += (size_t)blockIdx.x * 128 * Kp;

    float acc[2][8][4];
    #pragma unroll
    for (int mt = 0; mt < 2; mt++)
        #pragma unroll
        for (int nt = 0; nt < 8; nt++)
            #pragma unroll
            for (int r = 0; r < 4; r++) acc[mt][nt][r] = 0.f;

    GEMM_MAINLOOP(acc)

    C += (size_t)blockIdx.y * 128 * N + blockIdx.x * 128;
    #pragma unroll
    for (int mt = 0; mt < 2; mt++) {
        const int r0 = mBase + mt * 16 + g;
        #pragma unroll
        for (int nt = 0; nt < 8; nt++) {
            const int c = nBase + nt * 8 + t * 2;
            *(float2*)&C[(size_t)r0 * N + c]       = make_float2(acc[mt][nt][0], acc[mt][nt][1]);
            *(float2*)&C[(size_t)(r0 + 8) * N + c] = make_float2(acc[mt][nt][2], acc[mt][nt][3]);
        }
    }
}

// ---------------- fp16 tensor-core causal flash attention ----------------
#define APS 36
#define A_PH 0
#define A_PL 4608
#define A_KV 9216
#define KV_KH 0
#define KV_VH 2304
#define KV_STAGE 4608
#define A_MSK (A_KV + 2*KV_STAGE)
#define SMEM_ATTN_U32 (A_MSK + S_)

__device__ __forceinline__ void attn_stage_load(
    uint32_t* sma, int st, const uint32_t* kh, const uint32_t* vh, int kt, int tid)
{
    uint32_t* base = sma + A_KV + st * KV_STAGE;
    const int r = tid >> 2, c = tid & 3;
    const size_t gk = (size_t)(kt * 64 + r) * 32;
    cp16(&base[KV_KH + r * APS + c * 4],       kh + gk + c * 4);
    cp16(&base[KV_KH + r * APS + (c + 4) * 4], kh + gk + (c + 4) * 4);
    cp16(&base[KV_VH + r * APS + c * 4],       vh + gk + c * 4);
    cp16(&base[KV_VH + r * APS + (c + 4) * 4], vh + gk + (c + 4) * 4);
}

__global__ __launch_bounds__(256, 2) void attn_tc_kernel(const int* __restrict__ amask) {
    extern __shared__ uint32_t sma[];
    uint32_t* sPh = sma + A_PH;
    uint32_t* sPl = sma + A_PL;
    float* sMf = (float*)(sma + A_MSK);

    const int tid  = threadIdx.x;
    const int warp = tid >> 5;
    const int lane = tid & 31;
    const int g = lane >> 2;
    const int t = lane & 3;
    // LPT ordering: heaviest q-tiles first
    const int qtile = (S_ / 128 - 1) - (int)(blockIdx.x >> 5);
    const int bh    = blockIdx.x & 31;
    const int b  = bh >> 4;
    const int h  = bh & 15;
    const int qbase = qtile * 128;
    const int wrow  = warp * 16;

    const int r8 = lane & 7;
    const int aR = ((lane >> 3) & 1) * 8 + r8;
    const int aC = ((lane >> 4) & 1) * 4;
    const int bR = ((lane >> 4) & 1) * 8 + r8;
    const int bC = ((lane >> 3) & 1) * 4;
    const int vR = ((lane >> 3) & 1) * 8 + r8;
    const int vC = ((lane >> 4) & 1) * 4;
    const uint32_t smB = (uint32_t)__cvta_generic_to_shared(sma);

    const uint32_t* kh = g_khi + (size_t)bh * S_ * 32;
    const uint32_t* vh = g_vhi + (size_t)bh * S_ * 32;

    const int nkt = (qbase + 128) / 64;

    attn_stage_load(sma, 0, kh, vh, 0, tid);
    cp_commit();

    {
        const uint32_t* qgh = g_qhi + ((size_t)bh * S_ + qbase) * 32;
        const uint32_t* qgl = g_qlo + ((size_t)bh * S_ + qbase) * 32;
        for (int idx = tid; idx < 1024; idx += 256) {
            int r = idx >> 3, c4 = (idx & 7) * 4;
            *(uint4*)&sPh[r * APS + c4] = *(const uint4*)(qgh + r * 32 + c4);
            *(uint4*)&sPl[r * APS + c4] = *(const uint4*)(qgl + r * 32 + c4);
        }
        for (int idx = tid; idx < S_; idx += 256)
            sMf[idx] = (amask[b * S_ + idx] == 0) ? -INFINITY : 0.f;
    }
    __syncthreads();

    uint32_t Qh[4][4], Ql[4][4];
    #pragma unroll
    for (int ks = 0; ks < 4; ks++) {
        const uint32_t qaddr = smB + (((wrow + aR) * APS + ks * 8 + aC) << 2);
        ldsm4(Qh[ks], qaddr);
        ldsm4(Ql[ks], qaddr + A_PL * 4);
    }

    float oacc[8][4];
    #pragma unroll
    for (int nt = 0; nt < 8; nt++)
        #pragma unroll
        for (int r = 0; r < 4; r++) oacc[nt][r] = 0.f;
    float mrun[2] = {-INFINITY, -INFINITY};
    float lrun[2] = {0.f, 0.f};

    for (int kt = 0; kt < nkt; kt++) {
        if (kt + 1 < nkt) {
            attn_stage_load(sma, (kt + 1) & 1, kh, vh, kt + 1, tid);
            cp_commit();
            cp_wait<1>();
        } else {
            cp_wait<0>();
        }
        __syncthreads();

        if (kt * 64 <= qbase + wrow + 15) {
            const uint32_t kvB = smB + ((A_KV + (kt & 1) * KV_STAGE) << 2);

            // ---- S = Q K^T  (hi pass per ks, then lo pass) ----
            float sacc[8][4];
            #pragma unroll
            for (int nt = 0; nt < 8; nt++)
                #pragma unroll
                for (int r = 0; r < 4; r++) sacc[nt][r] = 0.f;

            #pragma unroll
            for (int ks = 0; ks < 4; ks++) {
                uint32_t bb[4][4];
                #pragma unroll
                for (int ntp = 0; ntp < 4; ntp++)
                    ldsm4(bb[ntp], kvB + ((KV_KH + (ntp * 16 + bR) * APS + ks * 8 + bC) << 2));
                #pragma unroll
                for (int ntp = 0; ntp < 4; ntp++) {
                    mma_f16(sacc[2 * ntp],     Qh[ks], bb[ntp]);
                    mma_f16(sacc[2 * ntp + 1], Qh[ks], bb[ntp] + 2);
                }
                #pragma unroll
                for (int ntp = 0; ntp < 4; ntp++) {
                    mma_f16(sacc[2 * ntp],     Ql[ks], bb[ntp]);
                    mma_f16(sacc[2 * ntp + 1], Ql[ks], bb[ntp] + 2);
                }
            }

            // ---- masks + row max (log2 domain) ----
            const bool diag = (kt * 64 + 63) > (qbase + wrow);
            float tmax[2] = {-INFINITY, -INFINITY};
            #pragma unroll
            for (int nt = 0; nt < 8; nt++) {
                #pragma unroll
                for (int e = 0; e < 4; e++) {
                    const int colL = nt * 8 + t * 2 + (e & 1);
                    float v = sacc[nt][e] + sMf[kt * 64 + colL];
                    if (diag) {
                        const int row = qbase + wrow + g + ((e >> 1) << 3);
                        const int col = kt * 64 + colL;
                        if (col > row) v = -INFINITY;
                    }
                    sacc[nt][e] = v;
                    tmax[e >> 1] = fmaxf(tmax[e >> 1], v);
                }
            }
            #pragma unroll
            for (int i = 0; i < 2; i++) {
                tmax[i] = fmaxf(tmax[i], __shfl_xor_sync(0xffffffff, tmax[i], 1));
                tmax[i] = fmaxf(tmax[i], __shfl_xor_sync(0xffffffff, tmax[i], 2));
            }

            // ---- online softmax (base-2); pack P frags IN REGISTERS over sacc ----
            float corr[2], psum[2] = {0.f, 0.f};
            #pragma unroll
            for (int i = 0; i < 2; i++) {
                float mnew = fmaxf(mrun[i], tmax[i]);
                corr[i] = fexp2(mrun[i] - mnew);
                mrun[i] = mnew;
                lrun[i] *= corr[i];
            }
            #pragma unroll
            for (int nt = 0; nt < 8; nt++) {
                oacc[nt][0] *= corr[0]; oacc[nt][1] *= corr[0];
                oacc[nt][2] *= corr[1]; oacc[nt][3] *= corr[1];
            }
            // For each (nt, half): two p's -> one hi word (stored at [half*2]) and
            // one lo word (stored at [half*2+1]), overwriting sacc in place.
            #pragma unroll
            for (int nt = 0; nt < 8; nt++) {
                #pragma unroll
                for (int half = 0; half < 2; half++) {
                    float p0 = fexp2(sacc[nt][half * 2 + 0] - mrun[half]);
                    float p1 = fexp2(sacc[nt][half * 2 + 1] - mrun[half]);
                    psum[half] += p0 + p1;
                    float h0 = hhi(p0), h1 = hhi(p1);
                    uint32_t hw = packh(h0, h1);
                    uint32_t lw = packh(p0 - h0, p1 - h1);
                    sacc[nt][half * 2 + 0] = __uint_as_float(hw);
                    sacc[nt][half * 2 + 1] = __uint_as_float(lw);
                }
            }
            #pragma unroll
            for (int i = 0; i < 2; i++) {
                psum[i] += __shfl_xor_sync(0xffffffff, psum[i], 1);
                psum[i] += __shfl_xor_sync(0xffffffff, psum[i], 2);
                lrun[i] += psum[i];
            }

            // ---- O += P V  (P frags straight from registers; V trans frags) ----
            #pragma unroll
            for (int ks = 0; ks < 4; ks++) {
                uint32_t ph4[4], pl4[4];
                ph4[0] = __float_as_uint(sacc[2 * ks][0]);
                ph4[1] = __float_as_uint(sacc[2 * ks][2]);
                ph4[2] = __float_as_uint(sacc[2 * ks + 1][0]);
                ph4[3] = __float_as_uint(sacc[2 * ks + 1][2]);
                pl4[0] = __float_as_uint(sacc[2 * ks][1]);
                pl4[1] = __float_as_uint(sacc[2 * ks][3]);
                pl4[2] = __float_as_uint(sacc[2 * ks + 1][1]);
                pl4[3] = __float_as_uint(sacc[2 * ks + 1][3]);
                uint32_t vv[4][4];
                #pragma unroll
                for (int ntp = 0; ntp < 4; ntp++)
                    ldsm4t(vv[ntp], kvB + ((KV_VH + (ks * 16 + vR) * APS + ntp * 8 + vC) << 2));
                #pragma unroll
                for (int ntp = 0; ntp < 4; ntp++) {
                    mma_f16(oacc[2 * ntp],     ph4, vv[ntp]);
                    mma_f16(oacc[2 * ntp + 1], ph4, vv[ntp] + 2);
                }
                #pragma unroll
                for (int ntp = 0; ntp < 4; ntp++) {
                    mma_f16(oacc[2 * ntp],     pl4, vv[ntp]);
                    mma_f16(oacc[2 * ntp + 1], pl4, vv[ntp] + 2);
                }
            }
        }
        __syncthreads();
    }

    // ---- epilogue: o/l, fp16 split, packed write ----
    const float inv0 = 1.f / lrun[0];
    const float inv1 = 1.f / lrun[1];
    const int r0 = qbase + wrow + g;
    const int r1 = r0 + 8;
    #pragma unroll
    for (int nt = 0; nt < 8; nt++) {
        float v0 = oacc[nt][0] * inv0, v1 = oacc[nt][1] * inv0;
        float v2 = oacc[nt][2] * inv1, v3 = oacc[nt][3] * inv1;
        const size_t o0 = (size_t)(b * S_ + r0) * 512 + h * 32 + nt * 4 + t;
        const size_t o1 = (size_t)(b * S_ + r1) * 512 + h * 32 + nt * 4 + t;
        float h0 = hhi(v0), h1 = hhi(v1), h2 = hhi(v2), h3 = hhi(v3);
        g_yhi[o0] = packh(h0, h1);
        g_ylo[o0] = packh(v0 - h0, v1 - h1);
        g_yhi[o1] = packh(h2, h3);
        g_ylo[o1] = packh(v2 - h2, v3 - h3);
    }
}

// ---------------- launch ----------------
extern "C" void kernel_launch(void* const* d_in, const int* in_sizes, int n_in,
                              void* d_out, int out_size)
{
    const float* x     = (const float*)d_in[0];
    const float* w_qkv = (const float*)d_in[1];
    const float* w_o   = (const float*)d_in[2];
    const int*   amask = (const int*)d_in[3];
    float* out = (float*)d_out;

    uint32_t *xhi, *xlo, *wqh, *woh, *yhi, *ylo;
    cudaGetSymbolAddress((void**)&xhi, g_xhi);
    cudaGetSymbolAddress((void**)&xlo, g_xlo);
    cudaGetSymbolAddress((void**)&wqh, g_wqh);
    cudaGetSymbolAddress((void**)&woh, g_woh);
    cudaGetSymbolAddress((void**)&yhi, g_yhi);
    cudaGetSymbolAddress((void**)&ylo, g_ylo);

    const int smem_gemm = SMEM_GEMM_U32 * 4;
    cudaFuncSetAttribute(qkv_gemm_rope_kernel,
                         cudaFuncAttributeMaxDynamicSharedMemorySize, smem_gemm);
    cudaFuncSetAttribute(f16_gemm_kernel,
                         cudaFuncAttributeMaxDynamicSharedMemorySize, smem_gemm);
    const int smem_attn = SMEM_ATTN_U32 * 4;
    cudaFuncSetAttribute(attn_tc_kernel,
                         cudaFuncAttributeMaxDynamicSharedMemorySize, smem_attn);

    rope_table_kernel<<<256, 256>>>();

    split2_kernel<<<(B_*S_*D_/2 + 255) / 256, 256>>>(x, xhi, xlo, B_*S_*D_/2);
    wsplit_t_kernel<<<dim3(3*D_/32, D_/32), 256>>>(w_qkv, wqh, D_, 3*D_);
    wsplit_t_kernel<<<dim3(D_/32, D_/32), 256>>>(w_o, woh, D_, D_);

    // QKV = x @ w_qkv with fused RoPE + split epilogue
    qkv_gemm_rope_kernel<<<dim3(3*D_/128, B_*S_/128), 256, smem_gemm>>>(xhi, xlo, wqh);

    attn_tc_kernel<<<(S_/128) * B_ * H_, 256, smem_attn>>>(amask);

    // out = y @ w_o
    f16_gemm_kernel<<<dim3(D_/128, B_*S_/128), 256, smem_gemm>>>(
        yhi, ylo, woh, out, B_*S_, D_, D_);
}

// round 13
// speedup vs baseline: 1.0675x; 1.0479x over previous
#include <cuda_runtime.h>
#include <cuda_fp16.h>
#include <math.h>
#include <stdint.h>

#define B_  2
#define S_  2048
#define D_  1024
#define H_  16
#define HD  64

// ---------------- scratch (device globals) ----------------
__device__ float g_cos[S_*32];
__device__ float g_sin[S_*32];
// fp16 packed pairs-along-K as uint32. A-side: hi+lo. B-side: hi only.
__device__ uint32_t g_xhi[B_*S_*D_/2],  g_xlo[B_*S_*D_/2];
__device__ uint32_t g_wqh[3*D_*D_/2];                       // transposed [N][K]
__device__ uint32_t g_woh[D_*D_/2];                         // transposed [N][K]
__device__ uint32_t g_qhi[B_*H_*S_*HD/2], g_qlo[B_*H_*S_*HD/2];
__device__ uint32_t g_khi[B_*H_*S_*HD/2];
__device__ uint32_t g_vhi[B_*H_*S_*HD/2];                   // V in K-layout [s][d]
__device__ uint32_t g_yhi[B_*S_*D_/2],  g_ylo[B_*S_*D_/2];

// ---------------- helpers ----------------
__device__ __forceinline__ float hhi(float v) {
    return __half2float(__float2half_rn(v));
}
__device__ __forceinline__ uint32_t packh(float f_low, float f_high) {
    uint32_t r;
    asm("cvt.rn.f16x2.f32 %0, %1, %2;" : "=r"(r) : "f"(f_high), "f"(f_low));
    return r;
}
__device__ __forceinline__ float fexp2(float x) {
    float r;
    asm("ex2.approx.f32 %0, %1;" : "=f"(r) : "f"(x));
    return r;
}
__device__ __forceinline__ void cp16(void* dst, const void* src) {
    uint32_t d = (uint32_t)__cvta_generic_to_shared(dst);
    asm volatile("cp.async.cg.shared.global [%0], [%1], 16;\n" :: "r"(d), "l"(src));
}
__device__ __forceinline__ void cp_commit() {
    asm volatile("cp.async.commit_group;\n");
}
template<int N> __device__ __forceinline__ void cp_wait() {
    asm volatile("cp.async.wait_group %0;\n" :: "n"(N));
}
__device__ __forceinline__ void mma_f16(float* d, const uint32_t* a, const uint32_t* b) {
    asm volatile(
        "mma.sync.aligned.m16n8k16.row.col.f32.f16.f16.f32 "
        "{%0,%1,%2,%3}, {%4,%5,%6,%7}, {%8,%9}, {%0,%1,%2,%3};\n"
        : "+f"(d[0]), "+f"(d[1]), "+f"(d[2]), "+f"(d[3])
        : "r"(a[0]), "r"(a[1]), "r"(a[2]), "r"(a[3]), "r"(b[0]), "r"(b[1]));
}
__device__ __forceinline__ void ldsm4(uint32_t* r, uint32_t saddr) {
    asm volatile("ldmatrix.sync.aligned.m8n8.x4.shared.b16 {%0,%1,%2,%3}, [%4];"
        : "=r"(r[0]), "=r"(r[1]), "=r"(r[2]), "=r"(r[3]) : "r"(saddr));
}
__device__ __forceinline__ void ldsm4t(uint32_t* r, uint32_t saddr) {
    asm volatile("ldmatrix.sync.aligned.m8n8.x4.trans.shared.b16 {%0,%1,%2,%3}, [%4];"
        : "=r"(r[0]), "=r"(r[1]), "=r"(r[2]), "=r"(r[3]) : "r"(saddr));
}

#define QSC_ (0.125f * 1.44269504088896340736f)   // 1/sqrt(64) * log2(e)

// ---------------- RoPE table ----------------
__global__ void rope_table_kernel() {
    int idx = blockIdx.x * 256 + threadIdx.x;
    if (idx >= S_ * 32) return;
    int s = idx >> 5;
    int j = idx & 31;
    double inv = pow(10000.0, -((double)(2 * j)) / 64.0);
    double ang = (double)s * inv;
    g_cos[idx] = (float)cos(ang);
    g_sin[idx] = (float)sin(ang);
}

// ---------------- elementwise fp16 hi/lo split (packed pairs) ----------------
__global__ __launch_bounds__(256) void split2_kernel(
    const float* __restrict__ src, uint32_t* __restrict__ hi, uint32_t* __restrict__ lo, int n2)
{
    int i = blockIdx.x * 256 + threadIdx.x;
    if (i >= n2) return;
    float2 v = ((const float2*)src)[i];
    float h0 = hhi(v.x), h1 = hhi(v.y);
    hi[i] = packh(h0, h1);
    lo[i] = packh(v.x - h0, v.y - h1);
}

// ---------------- weight transpose + fp16 quantize: w[K][N] -> wt[N][K] ----------------
__global__ __launch_bounds__(256) void wsplit_t_kernel(
    const float* __restrict__ w, uint32_t* __restrict__ th, int Kd, int Nd)
{
    __shared__ float tile[32][33];
    int n0 = blockIdx.x * 32, k0 = blockIdx.y * 32;
    int tx = threadIdx.x & 31, ty = threadIdx.x >> 5;
    #pragma unroll
    for (int r = 0; r < 32; r += 8)
        tile[ty + r][tx] = w[(size_t)(k0 + ty + r) * Nd + n0 + tx];
    __syncthreads();
    __half* thb = (__half*)th;
    #pragma unroll
    for (int r = 0; r < 32; r += 8) {
        int n = n0 + ty + r, k = k0 + tx;
        thb[(size_t)n * Kd + k] = __float2half_rn(tile[tx][ty + r]);
    }
}

// ---------------- shared GEMM plumbing ----------------
#define KS 20
#define G_AH 0
#define G_AL 2560
#define G_BH 5120
#define G_STAGE 7680
#define SMEM_GEMM_U32 (3*G_STAGE)

__device__ __forceinline__ void gemm_stage_load(
    uint32_t* st, const uint32_t* Ah, const uint32_t* Al, const uint32_t* Bh,
    int kp0, int tid, int Kp)
{
    const int row = tid >> 1;
    const int c = (tid & 1) * 8;
    const size_t ga = (size_t)row * Kp + kp0 + c;
    cp16(&st[G_AH + row * KS + c],     Ah + ga);
    cp16(&st[G_AH + row * KS + c + 4], Ah + ga + 4);
    cp16(&st[G_AL + row * KS + c],     Al + ga);
    cp16(&st[G_AL + row * KS + c + 4], Al + ga + 4);
    cp16(&st[G_BH + row * KS + c],     Bh + ga);
    cp16(&st[G_BH + row * KS + c + 4], Bh + ga + 4);
}

// mainloop: hi-pass then lo-pass so dependent-acc MMAs sit far apart
#define GEMM_MAINLOOP(ACC)                                                              \
    const int NT = Kp / 16;                                                             \
    gemm_stage_load(smg, Ahi, Alo, Bhi, 0, tid, Kp);                                    \
    cp_commit();                                                                        \
    gemm_stage_load(smg + G_STAGE, Ahi, Alo, Bhi, 16, tid, Kp);                         \
    cp_commit();                                                                        \
    int stage = 0;                                                                      \
    for (int it = 0; it < NT; it++) {                                                   \
        cp_wait<1>();                                                                   \
        __syncthreads();                                                                \
        if (it + 2 < NT) {                                                              \
            int s2 = stage + 2; if (s2 >= 3) s2 -= 3;                                   \
            gemm_stage_load(smg + s2 * G_STAGE, Ahi, Alo, Bhi, (it + 2) * 16, tid, Kp); \
        }                                                                               \
        cp_commit();                                                                    \
        const uint32_t stB = smB + (stage * G_STAGE) * 4;                               \
        _Pragma("unroll")                                                               \
        for (int kstep = 0; kstep < 2; kstep++) {                                       \
            const int k8 = kstep * 8;                                                   \
            uint32_t ah[2][4], al[2][4];                                                \
            _Pragma("unroll")                                                           \
            for (int mt = 0; mt < 2; mt++) {                                            \
                const uint32_t ab = stB + ((G_AH + (mBase + mt*16 + aR)*KS + k8 + aC) << 2); \
                ldsm4(ah[mt], ab);                                                      \
                ldsm4(al[mt], ab + (G_AL - G_AH) * 4);                                  \
            }                                                                           \
            uint32_t bb[4][4];                                                          \
            _Pragma("unroll")                                                           \
            for (int ntp = 0; ntp < 4; ntp++)                                           \
                ldsm4(bb[ntp], stB + ((G_BH + (nBase + ntp*16 + bR)*KS + k8 + bC) << 2)); \
            _Pragma("unroll")                                                           \
            for (int ntp = 0; ntp < 4; ntp++)                                           \
                _Pragma("unroll")                                                       \
                for (int mt = 0; mt < 2; mt++) {                                        \
                    mma_f16(ACC[mt][2*ntp],     ah[mt], bb[ntp]);                       \
                    mma_f16(ACC[mt][2*ntp + 1], ah[mt], bb[ntp] + 2);                   \
                }                                                                       \
            _Pragma("unroll")                                                           \
            for (int ntp = 0; ntp < 4; ntp++)                                           \
                _Pragma("unroll")                                                       \
                for (int mt = 0; mt < 2; mt++) {                                        \
                    mma_f16(ACC[mt][2*ntp],     al[mt], bb[ntp]);                       \
                    mma_f16(ACC[mt][2*ntp + 1], al[mt], bb[ntp] + 2);                   \
                }                                                                       \
        }                                                                               \
        if (++stage == 3) stage = 0;                                                    \
    }

// ---------------- QKV GEMM with fused RoPE + fp16 split epilogue ----------------
__global__ __launch_bounds__(256, 2) void qkv_gemm_rope_kernel(
    const uint32_t* __restrict__ Ahi, const uint32_t* __restrict__ Alo,
    const uint32_t* __restrict__ Bhi)
{
    extern __shared__ uint32_t smg[];
    const int Kp = D_ >> 1;
    const int tid  = threadIdx.x;
    const int warp = tid >> 5;
    const int lane = tid & 31;
    const int g = lane >> 2;
    const int t = lane & 3;
    const int mBase = (warp >> 1) * 32;
    const int nBase = (warp & 1) * 64;

    const int r8 = lane & 7;
    const int aR = ((lane >> 3) & 1) * 8 + r8;
    const int aC = ((lane >> 4) & 1) * 4;
    const int bR = ((lane >> 4) & 1) * 8 + r8;
    const int bC = ((lane >> 3) & 1) * 4;
    const uint32_t smB = (uint32_t)__cvta_generic_to_shared(smg);

    Ahi += (size_t)blockIdx.y * 128 * Kp;
    Alo += (size_t)blockIdx.y * 128 * Kp;
    Bhi += (size_t)blockIdx.x * 128 * Kp;

    float acc[2][8][4];
    #pragma unroll
    for (int mt = 0; mt < 2; mt++)
        #pragma unroll
        for (int nt = 0; nt < 8; nt++)
            #pragma unroll
            for (int r = 0; r < 4; r++) acc[mt][nt][r] = 0.f;

    GEMM_MAINLOOP(acc)

    // ---- fused epilogue: RoPE (q,k) + fp16 split, V passthrough quantize ----
    const int gcolbase = blockIdx.x * 128 + nBase;   // multiple of 64
    const int region = gcolbase >> 10;               // 0=q 1=k 2=v
    const int head   = (gcolbase & 1023) >> 6;

    #pragma unroll
    for (int mt = 0; mt < 2; mt++) {
        #pragma unroll
        for (int rs = 0; rs < 2; rs++) {
            const int m = blockIdx.y * 128 + mBase + mt * 16 + g + rs * 8;
            const int b = m >> 11, s = m & 2047;
            const size_t dbase = ((size_t)(b * 16 + head) * S_ + s) * 32;
            if (region == 2) {
                #pragma unroll
                for (int nt = 0; nt < 8; nt++) {
                    float v0 = acc[mt][nt][rs * 2 + 0];
                    float v1 = acc[mt][nt][rs * 2 + 1];
                    g_vhi[dbase + nt * 4 + t] = packh(hhi(v0), hhi(v1));
                }
            } else {
                #pragma unroll
                for (int nt = 0; nt < 8; nt++) {
                    const int i0 = nt * 8 + t * 2;
                    const int j0 = i0 & 31;
                    float c0 = g_cos[s * 32 + j0], c1 = g_cos[s * 32 + j0 + 1];
                    float s0 = g_sin[s * 32 + j0], s1 = g_sin[s * 32 + j0 + 1];
                    float sg = (i0 < 32) ? -1.f : 1.f;
                    float v0 = acc[mt][nt][rs * 2 + 0];
                    float v1 = acc[mt][nt][rs * 2 + 1];
                    float p0 = acc[mt][nt ^ 4][rs * 2 + 0];
                    float p1 = acc[mt][nt ^ 4][rs * 2 + 1];
                    float r0 = v0 * c0 + sg * p0 * s0;
                    float r1 = v1 * c1 + sg * p1 * s1;
                    if (region == 0) {
                        r0 *= QSC_; r1 *= QSC_;
                        float h0 = hhi(r0), h1 = hhi(r1);
                        g_qhi[dbase + nt * 4 + t] = packh(h0, h1);
                        g_qlo[dbase + nt * 4 + t] = packh(r0 - h0, r1 - h1);
                    } else {
                        g_khi[dbase + nt * 4 + t] = packh(hhi(r0), hhi(r1));
                    }
                }
            }
        }
    }
}

// ---------------- generic fp16 2-product GEMM (O-proj) ----------------
__global__ __launch_bounds__(256, 2) void f16_gemm_kernel(
    const uint32_t* __restrict__ Ahi, const uint32_t* __restrict__ Alo,
    const uint32_t* __restrict__ Bhi,
    float* __restrict__ C, int M, int N, int K)
{
    extern __shared__ uint32_t smg[];
    const int Kp = K >> 1;
    const int tid  = threadIdx.x;
    const int warp = tid >> 5;
    const int lane = tid & 31;
    const int g = lane >> 2;
    const int t = lane & 3;
    const int mBase = (warp >> 1) * 32;
    const int nBase = (warp & 1) * 64;

    const int r8 = lane & 7;
    const int aR = ((lane >> 3) & 1) * 8 + r8;
    const int aC = ((lane >> 4) & 1) * 4;
    const int bR = ((lane >> 4) & 1) * 8 + r8;
    const int bC = ((lane >> 3) & 1) * 4;
    const uint32_t smB = (uint32_t)__cvta_generic_to_shared(smg);

    Ahi += (size_t)blockIdx.y * 128 * Kp;
    Alo += (size_t)blockIdx.y * 128 * Kp;
    Bhi += (size_t)blockIdx.x * 128 * Kp;

    float acc[2][8][4];
    #pragma unroll
    for (int mt = 0; mt < 2; mt++)
        #pragma unroll
        for (int nt = 0; nt < 8; nt++)
            #pragma unroll
            for (int r = 0; r < 4; r++) acc[mt][nt][r] = 0.f;

    GEMM_MAINLOOP(acc)

    C += (size_t)blockIdx.y * 128 * N + blockIdx.x * 128;
    #pragma unroll
    for (int mt = 0; mt < 2; mt++) {
        const int r0 = mBase + mt * 16 + g;
        #pragma unroll
        for (int nt = 0; nt < 8; nt++) {
            const int c = nBase + nt * 8 + t * 2;
            *(float2*)&C[(size_t)r0 * N + c]       = make_float2(acc[mt][nt][0], acc[mt][nt][1]);
            *(float2*)&C[(size_t)(r0 + 8) * N + c] = make_float2(acc[mt][nt][2], acc[mt][nt][3]);
        }
    }
}

// ---------------- fp16 tensor-core causal flash attention ----------------
#define APS 36
#define A_PH 0
#define A_PL 4608
#define A_KV 9216
#define KV_KH 0
#define KV_VH 2304
#define KV_STAGE 4608
#define A_MSK (A_KV + 2*KV_STAGE)
#define SMEM_ATTN_U32 (A_MSK + S_)

__device__ __forceinline__ void attn_stage_load(
    uint32_t* sma, int st, const uint32_t* kh, const uint32_t* vh, int kt, int tid)
{
    uint32_t* base = sma + A_KV + st * KV_STAGE;
    const int r = tid >> 2, c = tid & 3;
    const size_t gk = (size_t)(kt * 64 + r) * 32;
    cp16(&base[KV_KH + r * APS + c * 4],       kh + gk + c * 4);
    cp16(&base[KV_KH + r * APS + (c + 4) * 4], kh + gk + (c + 4) * 4);
    cp16(&base[KV_VH + r * APS + c * 4],       vh + gk + c * 4);
    cp16(&base[KV_VH + r * APS + (c + 4) * 4], vh + gk + (c + 4) * 4);
}

__global__ __launch_bounds__(256, 2) void attn_tc_kernel(const int* __restrict__ amask) {
    extern __shared__ uint32_t sma[];
    uint32_t* sPh = sma + A_PH;
    uint32_t* sPl = sma + A_PL;
    float* sMf = (float*)(sma + A_MSK);

    const int tid  = threadIdx.x;
    const int warp = tid >> 5;
    const int lane = tid & 31;
    const int g = lane >> 2;
    const int t = lane & 3;
    // LPT ordering: heaviest q-tiles first
    const int qtile = (S_ / 128 - 1) - (int)(blockIdx.x >> 5);
    const int bh    = blockIdx.x & 31;
    const int b  = bh >> 4;
    const int h  = bh & 15;
    const int qbase = qtile * 128;
    const int wrow  = warp * 16;

    const int r8 = lane & 7;
    const int aR = ((lane >> 3) & 1) * 8 + r8;
    const int aC = ((lane >> 4) & 1) * 4;
    const int bR = ((lane >> 4) & 1) * 8 + r8;
    const int bC = ((lane >> 3) & 1) * 4;
    const int vR = ((lane >> 3) & 1) * 8 + r8;
    const int vC = ((lane >> 4) & 1) * 4;
    const uint32_t smB = (uint32_t)__cvta_generic_to_shared(sma);

    const uint32_t* kh = g_khi + (size_t)bh * S_ * 32;
    const uint32_t* vh = g_vhi + (size_t)bh * S_ * 32;

    const int nkt = (qbase + 128) / 64;

    attn_stage_load(sma, 0, kh, vh, 0, tid);
    cp_commit();

    {
        const uint32_t* qgh = g_qhi + ((size_t)bh * S_ + qbase) * 32;
        const uint32_t* qgl = g_qlo + ((size_t)bh * S_ + qbase) * 32;
        for (int idx = tid; idx < 1024; idx += 256) {
            int r = idx >> 3, c4 = (idx & 7) * 4;
            *(uint4*)&sPh[r * APS + c4] = *(const uint4*)(qgh + r * 32 + c4);
            *(uint4*)&sPl[r * APS + c4] = *(const uint4*)(qgl + r * 32 + c4);
        }
        for (int idx = tid; idx < S_; idx += 256)
            sMf[idx] = (amask[b * S_ + idx] == 0) ? -INFINITY : 0.f;
    }
    __syncthreads();

    uint32_t Qh[4][4], Ql[4][4];
    #pragma unroll
    for (int ks = 0; ks < 4; ks++) {
        const uint32_t qaddr = smB + (((wrow + aR) * APS + ks * 8 + aC) << 2);
        ldsm4(Qh[ks], qaddr);
        ldsm4(Ql[ks], qaddr + A_PL * 4);
    }

    float oacc[8][4];
    #pragma unroll
    for (int nt = 0; nt < 8; nt++)
        #pragma unroll
        for (int r = 0; r < 4; r++) oacc[nt][r] = 0.f;
    float mrun[2] = {-INFINITY, -INFINITY};
    float lrun[2] = {0.f, 0.f};

    for (int kt = 0; kt < nkt; kt++) {
        if (kt + 1 < nkt) {
            attn_stage_load(sma, (kt + 1) & 1, kh, vh, kt + 1, tid);
            cp_commit();
            cp_wait<1>();
        } else {
            cp_wait<0>();
        }
        __syncthreads();

        if (kt * 64 <= qbase + wrow + 15) {
            const uint32_t kvB = smB + ((A_KV + (kt & 1) * KV_STAGE) << 2);

            // ---- S = Q K^T  (hi pass per ks, then lo pass) ----
            float sacc[8][4];
            #pragma unroll
            for (int nt = 0; nt < 8; nt++)
                #pragma unroll
                for (int r = 0; r < 4; r++) sacc[nt][r] = 0.f;

            #pragma unroll
            for (int ks = 0; ks < 4; ks++) {
                uint32_t bb[4][4];
                #pragma unroll
                for (int ntp = 0; ntp < 4; ntp++)
                    ldsm4(bb[ntp], kvB + ((KV_KH + (ntp * 16 + bR) * APS + ks * 8 + bC) << 2));
                #pragma unroll
                for (int ntp = 0; ntp < 4; ntp++) {
                    mma_f16(sacc[2 * ntp],     Qh[ks], bb[ntp]);
                    mma_f16(sacc[2 * ntp + 1], Qh[ks], bb[ntp] + 2);
                }
                #pragma unroll
                for (int ntp = 0; ntp < 4; ntp++) {
                    mma_f16(sacc[2 * ntp],     Ql[ks], bb[ntp]);
                    mma_f16(sacc[2 * ntp + 1], Ql[ks], bb[ntp] + 2);
                }
            }

            // ---- masks + row max (log2 domain) ----
            const bool diag = (kt * 64 + 63) > (qbase + wrow);
            float tmax[2] = {-INFINITY, -INFINITY};
            #pragma unroll
            for (int nt = 0; nt < 8; nt++) {
                #pragma unroll
                for (int e = 0; e < 4; e++) {
                    const int colL = nt * 8 + t * 2 + (e & 1);
                    float v = sacc[nt][e] + sMf[kt * 64 + colL];
                    if (diag) {
                        const int row = qbase + wrow + g + ((e >> 1) << 3);
                        const int col = kt * 64 + colL;
                        if (col > row) v = -INFINITY;
                    }
                    sacc[nt][e] = v;
                    tmax[e >> 1] = fmaxf(tmax[e >> 1], v);
                }
            }
            #pragma unroll
            for (int i = 0; i < 2; i++) {
                tmax[i] = fmaxf(tmax[i], __shfl_xor_sync(0xffffffff, tmax[i], 1));
                tmax[i] = fmaxf(tmax[i], __shfl_xor_sync(0xffffffff, tmax[i], 2));
            }

            // ---- online softmax (base-2); pack P-hi frags IN REGISTERS over sacc ----
            float corr[2], psum[2] = {0.f, 0.f};
            #pragma unroll
            for (int i = 0; i < 2; i++) {
                float mnew = fmaxf(mrun[i], tmax[i]);
                corr[i] = fexp2(mrun[i] - mnew);
                mrun[i] = mnew;
                lrun[i] *= corr[i];
            }
            #pragma unroll
            for (int nt = 0; nt < 8; nt++) {
                oacc[nt][0] *= corr[0]; oacc[nt][1] *= corr[0];
                oacc[nt][2] *= corr[1]; oacc[nt][3] *= corr[1];
            }
            // For each (nt, half): two p's -> one fp16x2 hi word stored at [half*2].
            #pragma unroll
            for (int nt = 0; nt < 8; nt++) {
                #pragma unroll
                for (int half = 0; half < 2; half++) {
                    float p0 = fexp2(sacc[nt][half * 2 + 0] - mrun[half]);
                    float p1 = fexp2(sacc[nt][half * 2 + 1] - mrun[half]);
                    psum[half] += p0 + p1;
                    sacc[nt][half * 2] = __uint_as_float(packh(p0, p1));
                }
            }
            #pragma unroll
            for (int i = 0; i < 2; i++) {
                psum[i] += __shfl_xor_sync(0xffffffff, psum[i], 1);
                psum[i] += __shfl_xor_sync(0xffffffff, psum[i], 2);
                lrun[i] += psum[i];
            }

            // ---- O += P V  (P-hi frags from registers; V trans frags) ----
            #pragma unroll
            for (int ks = 0; ks < 4; ks++) {
                uint32_t ph4[4];
                ph4[0] = __float_as_uint(sacc[2 * ks][0]);
                ph4[1] = __float_as_uint(sacc[2 * ks][2]);
                ph4[2] = __float_as_uint(sacc[2 * ks + 1][0]);
                ph4[3] = __float_as_uint(sacc[2 * ks + 1][2]);
                uint32_t vv[4][4];
                #pragma unroll
                for (int ntp = 0; ntp < 4; ntp++)
                    ldsm4t(vv[ntp], kvB + ((KV_VH + (ks * 16 + vR) * APS + ntp * 8 + vC) << 2));
                #pragma unroll
                for (int ntp = 0; ntp < 4; ntp++) {
                    mma_f16(oacc[2 * ntp],     ph4, vv[ntp]);
                    mma_f16(oacc[2 * ntp + 1], ph4, vv[ntp] + 2);
                }
            }
        }
        __syncthreads();
    }

    // ---- epilogue: o/l, fp16 split, packed write ----
    const float inv0 = 1.f / lrun[0];
    const float inv1 = 1.f / lrun[1];
    const int r0 = qbase + wrow + g;
    const int r1 = r0 + 8;
    #pragma unroll
    for (int nt = 0; nt < 8; nt++) {
        float v0 = oacc[nt][0] * inv0, v1 = oacc[nt][1] * inv0;
        float v2 = oacc[nt][2] * inv1, v3 = oacc[nt][3] * inv1;
        const size_t o0 = (size_t)(b * S_ + r0) * 512 + h * 32 + nt * 4 + t;
        const size_t o1 = (size_t)(b * S_ + r1) * 512 + h * 32 + nt * 4 + t;
        float h0 = hhi(v0), h1 = hhi(v1), h2 = hhi(v2), h3 = hhi(v3);
        g_yhi[o0] = packh(h0, h1);
        g_ylo[o0] = packh(v0 - h0, v1 - h1);
        g_yhi[o1] = packh(h2, h3);
        g_ylo[o1] = packh(v2 - h2, v3 - h3);
    }
}

// ---------------- launch ----------------
extern "C" void kernel_launch(void* const* d_in, const int* in_sizes, int n_in,
                              void* d_out, int out_size)
{
    const float* x     = (const float*)d_in[0];
    const float* w_qkv = (const float*)d_in[1];
    const float* w_o   = (const float*)d_in[2];
    const int*   amask = (const int*)d_in[3];
    float* out = (float*)d_out;

    uint32_t *xhi, *xlo, *wqh, *woh, *yhi, *ylo;
    cudaGetSymbolAddress((void**)&xhi, g_xhi);
    cudaGetSymbolAddress((void**)&xlo, g_xlo);
    cudaGetSymbolAddress((void**)&wqh, g_wqh);
    cudaGetSymbolAddress((void**)&woh, g_woh);
    cudaGetSymbolAddress((void**)&yhi, g_yhi);
    cudaGetSymbolAddress((void**)&ylo, g_ylo);

    const int smem_gemm = SMEM_GEMM_U32 * 4;
    cudaFuncSetAttribute(qkv_gemm_rope_kernel,
                         cudaFuncAttributeMaxDynamicSharedMemorySize, smem_gemm);
    cudaFuncSetAttribute(f16_gemm_kernel,
                         cudaFuncAttributeMaxDynamicSharedMemorySize, smem_gemm);
    const int smem_attn = SMEM_ATTN_U32 * 4;
    cudaFuncSetAttribute(attn_tc_kernel,
                         cudaFuncAttributeMaxDynamicSharedMemorySize, smem_attn);

    rope_table_kernel<<<256, 256>>>();

    split2_kernel<<<(B_*S_*D_/2 + 255) / 256, 256>>>(x, xhi, xlo, B_*S_*D_/2);
    wsplit_t_kernel<<<dim3(3*D_/32, D_/32), 256>>>(w_qkv, wqh, D_, 3*D_);
    wsplit_t_kernel<<<dim3(D_/32, D_/32), 256>>>(w_o, woh, D_, D_);

    // QKV = x @ w_qkv with fused RoPE + split epilogue
    qkv_gemm_rope_kernel<<<dim3(3*D_/128, B_*S_/128), 256, smem_gemm>>>(xhi, xlo, wqh);

    attn_tc_kernel<<<(S_/128) * B_ * H_, 256, smem_attn>>>(amask);

    // out = y @ w_o
    f16_gemm_kernel<<<dim3(D_/128, B_*S_/128), 256, smem_gemm>>>(
        yhi, ylo, woh, out, B_*S_, D_, D_);
}

// round 14
// speedup vs baseline: 1.1404x; 1.0682x over previous
#include <cuda_runtime.h>
#include <cuda_fp16.h>
#include <math.h>
#include <stdint.h>

#define B_  2
#define S_  2048
#define D_  1024
#define H_  16
#define HD  64

// ---------------- scratch (device globals) ----------------
__device__ float g_cos[S_*32];
__device__ float g_sin[S_*32];
// fp16 packed pairs-along-K as uint32. x: hi+lo. weights/Q/K/V: hi only.
__device__ uint32_t g_xhi[B_*S_*D_/2],  g_xlo[B_*S_*D_/2];
__device__ uint32_t g_wqh[3*D_*D_/2];                       // transposed [N][K]
__device__ uint32_t g_woh[D_*D_/2];                         // transposed [N][K]
__device__ uint32_t g_qhi[B_*H_*S_*HD/2];
__device__ uint32_t g_khi[B_*H_*S_*HD/2];
__device__ uint32_t g_vhi[B_*H_*S_*HD/2];                   // V in K-layout [s][d]
__device__ uint32_t g_yhi[B_*S_*D_/2],  g_ylo[B_*S_*D_/2];

// ---------------- helpers ----------------
__device__ __forceinline__ float hhi(float v) {
    return __half2float(__float2half_rn(v));
}
__device__ __forceinline__ uint32_t packh(float f_low, float f_high) {
    uint32_t r;
    asm("cvt.rn.f16x2.f32 %0, %1, %2;" : "=r"(r) : "f"(f_high), "f"(f_low));
    return r;
}
__device__ __forceinline__ float fexp2(float x) {
    float r;
    asm("ex2.approx.f32 %0, %1;" : "=f"(r) : "f"(x));
    return r;
}
__device__ __forceinline__ void cp16(void* dst, const void* src) {
    uint32_t d = (uint32_t)__cvta_generic_to_shared(dst);
    asm volatile("cp.async.cg.shared.global [%0], [%1], 16;\n" :: "r"(d), "l"(src));
}
__device__ __forceinline__ void cp_commit() {
    asm volatile("cp.async.commit_group;\n");
}
template<int N> __device__ __forceinline__ void cp_wait() {
    asm volatile("cp.async.wait_group %0;\n" :: "n"(N));
}
__device__ __forceinline__ void mma_f16(float* d, const uint32_t* a, const uint32_t* b) {
    asm volatile(
        "mma.sync.aligned.m16n8k16.row.col.f32.f16.f16.f32 "
        "{%0,%1,%2,%3}, {%4,%5,%6,%7}, {%8,%9}, {%0,%1,%2,%3};\n"
        : "+f"(d[0]), "+f"(d[1]), "+f"(d[2]), "+f"(d[3])
        : "r"(a[0]), "r"(a[1]), "r"(a[2]), "r"(a[3]), "r"(b[0]), "r"(b[1]));
}
__device__ __forceinline__ void ldsm4(uint32_t* r, uint32_t saddr) {
    asm volatile("ldmatrix.sync.aligned.m8n8.x4.shared.b16 {%0,%1,%2,%3}, [%4];"
        : "=r"(r[0]), "=r"(r[1]), "=r"(r[2]), "=r"(r[3]) : "r"(saddr));
}
__device__ __forceinline__ void ldsm4t(uint32_t* r, uint32_t saddr) {
    asm volatile("ldmatrix.sync.aligned.m8n8.x4.trans.shared.b16 {%0,%1,%2,%3}, [%4];"
        : "=r"(r[0]), "=r"(r[1]), "=r"(r[2]), "=r"(r[3]) : "r"(saddr));
}

#define QSC_ (0.125f * 1.44269504088896340736f)   // 1/sqrt(64) * log2(e)

// ---------------- RoPE table ----------------
__global__ void rope_table_kernel() {
    int idx = blockIdx.x * 256 + threadIdx.x;
    if (idx >= S_ * 32) return;
    int s = idx >> 5;
    int j = idx & 31;
    double inv = pow(10000.0, -((double)(2 * j)) / 64.0);
    double ang = (double)s * inv;
    g_cos[idx] = (float)cos(ang);
    g_sin[idx] = (float)sin(ang);
}

// ---------------- elementwise fp16 hi/lo split (packed pairs) ----------------
__global__ __launch_bounds__(256) void split2_kernel(
    const float* __restrict__ src, uint32_t* __restrict__ hi, uint32_t* __restrict__ lo, int n2)
{
    int i = blockIdx.x * 256 + threadIdx.x;
    if (i >= n2) return;
    float2 v = ((const float2*)src)[i];
    float h0 = hhi(v.x), h1 = hhi(v.y);
    hi[i] = packh(h0, h1);
    lo[i] = packh(v.x - h0, v.y - h1);
}

// ---------------- weight transpose + fp16 quantize: w[K][N] -> wt[N][K] ----------------
__global__ __launch_bounds__(256) void wsplit_t_kernel(
    const float* __restrict__ w, uint32_t* __restrict__ th, int Kd, int Nd)
{
    __shared__ float tile[32][33];
    int n0 = blockIdx.x * 32, k0 = blockIdx.y * 32;
    int tx = threadIdx.x & 31, ty = threadIdx.x >> 5;
    #pragma unroll
    for (int r = 0; r < 32; r += 8)
        tile[ty + r][tx] = w[(size_t)(k0 + ty + r) * Nd + n0 + tx];
    __syncthreads();
    __half* thb = (__half*)th;
    #pragma unroll
    for (int r = 0; r < 32; r += 8) {
        int n = n0 + ty + r, k = k0 + tx;
        thb[(size_t)n * Kd + k] = __float2half_rn(tile[tx][ty + r]);
    }
}

// ---------------- shared GEMM plumbing ----------------
#define KS 20
#define G_AH 0
#define G_AL 2560
#define G_BH 5120
#define G_STAGE 7680
#define SMEM_GEMM_U32 (3*G_STAGE)

__device__ __forceinline__ void gemm_stage_load(
    uint32_t* st, const uint32_t* Ah, const uint32_t* Al, const uint32_t* Bh,
    int kp0, int tid, int Kp)
{
    const int row = tid >> 1;
    const int c = (tid & 1) * 8;
    const size_t ga = (size_t)row * Kp + kp0 + c;
    cp16(&st[G_AH + row * KS + c],     Ah + ga);
    cp16(&st[G_AH + row * KS + c + 4], Ah + ga + 4);
    cp16(&st[G_AL + row * KS + c],     Al + ga);
    cp16(&st[G_AL + row * KS + c + 4], Al + ga + 4);
    cp16(&st[G_BH + row * KS + c],     Bh + ga);
    cp16(&st[G_BH + row * KS + c + 4], Bh + ga + 4);
}

// mainloop: hi-pass then lo-pass so dependent-acc MMAs sit far apart
#define GEMM_MAINLOOP(ACC)                                                              \
    const int NT = Kp / 16;                                                             \
    gemm_stage_load(smg, Ahi, Alo, Bhi, 0, tid, Kp);                                    \
    cp_commit();                                                                        \
    gemm_stage_load(smg + G_STAGE, Ahi, Alo, Bhi, 16, tid, Kp);                         \
    cp_commit();                                                                        \
    int stage = 0;                                                                      \
    for (int it = 0; it < NT; it++) {                                                   \
        cp_wait<1>();                                                                   \
        __syncthreads();                                                                \
        if (it + 2 < NT) {                                                              \
            int s2 = stage + 2; if (s2 >= 3) s2 -= 3;                                   \
            gemm_stage_load(smg + s2 * G_STAGE, Ahi, Alo, Bhi, (it + 2) * 16, tid, Kp); \
        }                                                                               \
        cp_commit();                                                                    \
        const uint32_t stB = smB + (stage * G_STAGE) * 4;                               \
        _Pragma("unroll")                                                               \
        for (int kstep = 0; kstep < 2; kstep++) {                                       \
            const int k8 = kstep * 8;                                                   \
            uint32_t ah[2][4], al[2][4];                                                \
            _Pragma("unroll")                                                           \
            for (int mt = 0; mt < 2; mt++) {                                            \
                const uint32_t ab = stB + ((G_AH + (mBase + mt*16 + aR)*KS + k8 + aC) << 2); \
                ldsm4(ah[mt], ab);                                                      \
                ldsm4(al[mt], ab + (G_AL - G_AH) * 4);                                  \
            }                                                                           \
            uint32_t bb[4][4];                                                          \
            _Pragma("unroll")                                                           \
            for (int ntp = 0; ntp < 4; ntp++)                                           \
                ldsm4(bb[ntp], stB + ((G_BH + (nBase + ntp*16 + bR)*KS + k8 + bC) << 2)); \
            _Pragma("unroll")                                                           \
            for (int ntp = 0; ntp < 4; ntp++)                                           \
                _Pragma("unroll")                                                       \
                for (int mt = 0; mt < 2; mt++) {                                        \
                    mma_f16(ACC[mt][2*ntp],     ah[mt], bb[ntp]);                       \
                    mma_f16(ACC[mt][2*ntp + 1], ah[mt], bb[ntp] + 2);                   \
                }                                                                       \
            _Pragma("unroll")                                                           \
            for (int ntp = 0; ntp < 4; ntp++)                                           \
                _Pragma("unroll")                                                       \
                for (int mt = 0; mt < 2; mt++) {                                        \
                    mma_f16(ACC[mt][2*ntp],     al[mt], bb[ntp]);                       \
                    mma_f16(ACC[mt][2*ntp + 1], al[mt], bb[ntp] + 2);                   \
                }                                                                       \
        }                                                                               \
        if (++stage == 3) stage = 0;                                                    \
    }

// ---------------- QKV GEMM with fused RoPE + fp16 quantize epilogue ----------------
__global__ __launch_bounds__(256, 2) void qkv_gemm_rope_kernel(
    const uint32_t* __restrict__ Ahi, const uint32_t* __restrict__ Alo,
    const uint32_t* __restrict__ Bhi)
{
    extern __shared__ uint32_t smg[];
    const int Kp = D_ >> 1;
    const int tid  = threadIdx.x;
    const int warp = tid >> 5;
    const int lane = tid & 31;
    const int g = lane >> 2;
    const int t = lane & 3;
    const int mBase = (warp >> 1) * 32;
    const int nBase = (warp & 1) * 64;

    const int r8 = lane & 7;
    const int aR = ((lane >> 3) & 1) * 8 + r8;
    const int aC = ((lane >> 4) & 1) * 4;
    const int bR = ((lane >> 4) & 1) * 8 + r8;
    const int bC = ((lane >> 3) & 1) * 4;
    const uint32_t smB = (uint32_t)__cvta_generic_to_shared(smg);

    Ahi += (size_t)blockIdx.y * 128 * Kp;
    Alo += (size_t)blockIdx.y * 128 * Kp;
    Bhi += (size_t)blockIdx.x * 128 * Kp;

    float acc[2][8][4];
    #pragma unroll
    for (int mt = 0; mt < 2; mt++)
        #pragma unroll
        for (int nt = 0; nt < 8; nt++)
            #pragma unroll
            for (int r = 0; r < 4; r++) acc[mt][nt][r] = 0.f;

    GEMM_MAINLOOP(acc)

    // ---- fused epilogue: RoPE (q,k) + fp16 quantize, V passthrough quantize ----
    const int gcolbase = blockIdx.x * 128 + nBase;   // multiple of 64
    const int region = gcolbase >> 10;               // 0=q 1=k 2=v
    const int head   = (gcolbase & 1023) >> 6;

    #pragma unroll
    for (int mt = 0; mt < 2; mt++) {
        #pragma unroll
        for (int rs = 0; rs < 2; rs++) {
            const int m = blockIdx.y * 128 + mBase + mt * 16 + g + rs * 8;
            const int b = m >> 11, s = m & 2047;
            const size_t dbase = ((size_t)(b * 16 + head) * S_ + s) * 32;
            if (region == 2) {
                #pragma unroll
                for (int nt = 0; nt < 8; nt++) {
                    float v0 = acc[mt][nt][rs * 2 + 0];
                    float v1 = acc[mt][nt][rs * 2 + 1];
                    g_vhi[dbase + nt * 4 + t] = packh(hhi(v0), hhi(v1));
                }
            } else {
                #pragma unroll
                for (int nt = 0; nt < 8; nt++) {
                    const int i0 = nt * 8 + t * 2;
                    const int j0 = i0 & 31;
                    float c0 = g_cos[s * 32 + j0], c1 = g_cos[s * 32 + j0 + 1];
                    float s0 = g_sin[s * 32 + j0], s1 = g_sin[s * 32 + j0 + 1];
                    float sg = (i0 < 32) ? -1.f : 1.f;
                    float v0 = acc[mt][nt][rs * 2 + 0];
                    float v1 = acc[mt][nt][rs * 2 + 1];
                    float p0 = acc[mt][nt ^ 4][rs * 2 + 0];
                    float p1 = acc[mt][nt ^ 4][rs * 2 + 1];
                    float r0 = v0 * c0 + sg * p0 * s0;
                    float r1 = v1 * c1 + sg * p1 * s1;
                    if (region == 0) {
                        g_qhi[dbase + nt * 4 + t] = packh(hhi(r0 * QSC_), hhi(r1 * QSC_));
                    } else {
                        g_khi[dbase + nt * 4 + t] = packh(hhi(r0), hhi(r1));
                    }
                }
            }
        }
    }
}

// ---------------- generic fp16 2-product GEMM (O-proj) ----------------
__global__ __launch_bounds__(256, 2) void f16_gemm_kernel(
    const uint32_t* __restrict__ Ahi, const uint32_t* __restrict__ Alo,
    const uint32_t* __restrict__ Bhi,
    float* __restrict__ C, int M, int N, int K)
{
    extern __shared__ uint32_t smg[];
    const int Kp = K >> 1;
    const int tid  = threadIdx.x;
    const int warp = tid >> 5;
    const int lane = tid & 31;
    const int g = lane >> 2;
    const int t = lane & 3;
    const int mBase = (warp >> 1) * 32;
    const int nBase = (warp & 1) * 64;

    const int r8 = lane & 7;
    const int aR = ((lane >> 3) & 1) * 8 + r8;
    const int aC = ((lane >> 4) & 1) * 4;
    const int bR = ((lane >> 4) & 1) * 8 + r8;
    const int bC = ((lane >> 3) & 1) * 4;
    const uint32_t smB = (uint32_t)__cvta_generic_to_shared(smg);

    Ahi += (size_t)blockIdx.y * 128 * Kp;
    Alo += (size_t)blockIdx.y * 128 * Kp;
    Bhi += (size_t)blockIdx.x * 128 * Kp;

    float acc[2][8][4];
    #pragma unroll
    for (int mt = 0; mt < 2; mt++)
        #pragma unroll
        for (int nt = 0; nt < 8; nt++)
            #pragma unroll
            for (int r = 0; r < 4; r++) acc[mt][nt][r] = 0.f;

    GEMM_MAINLOOP(acc)

    C += (size_t)blockIdx.y * 128 * N + blockIdx.x * 128;
    #pragma unroll
    for (int mt = 0; mt < 2; mt++) {
        const int r0 = mBase + mt * 16 + g;
        #pragma unroll
        for (int nt = 0; nt < 8; nt++) {
            const int c = nBase + nt * 8 + t * 2;
            *(float2*)&C[(size_t)r0 * N + c]       = make_float2(acc[mt][nt][0], acc[mt][nt][1]);
            *(float2*)&C[(size_t)(r0 + 8) * N + c] = make_float2(acc[mt][nt][2], acc[mt][nt][3]);
        }
    }
}

// ---------------- fp16 tensor-core causal flash attention ----------------
#define APS 36
#define A_PH 0
#define A_KV 4608
#define KV_KH 0
#define KV_VH 2304
#define KV_STAGE 4608
#define A_MSK (A_KV + 2*KV_STAGE)
#define SMEM_ATTN_U32 (A_MSK + S_)

__device__ __forceinline__ void attn_stage_load(
    uint32_t* sma, int st, const uint32_t* kh, const uint32_t* vh, int kt, int tid)
{
    uint32_t* base = sma + A_KV + st * KV_STAGE;
    const int r = tid >> 2, c = tid & 3;
    const size_t gk = (size_t)(kt * 64 + r) * 32;
    cp16(&base[KV_KH + r * APS + c * 4],       kh + gk + c * 4);
    cp16(&base[KV_KH + r * APS + (c + 4) * 4], kh + gk + (c + 4) * 4);
    cp16(&base[KV_VH + r * APS + c * 4],       vh + gk + c * 4);
    cp16(&base[KV_VH + r * APS + (c + 4) * 4], vh + gk + (c + 4) * 4);
}

__global__ __launch_bounds__(256, 2) void attn_tc_kernel(const int* __restrict__ amask) {
    extern __shared__ uint32_t sma[];
    uint32_t* sPh = sma + A_PH;
    float* sMf = (float*)(sma + A_MSK);

    const int tid  = threadIdx.x;
    const int warp = tid >> 5;
    const int lane = tid & 31;
    const int g = lane >> 2;
    const int t = lane & 3;
    // LPT ordering: heaviest q-tiles first
    const int qtile = (S_ / 128 - 1) - (int)(blockIdx.x >> 5);
    const int bh    = blockIdx.x & 31;
    const int b  = bh >> 4;
    const int h  = bh & 15;
    const int qbase = qtile * 128;
    const int wrow  = warp * 16;

    const int r8 = lane & 7;
    const int aR = ((lane >> 3) & 1) * 8 + r8;
    const int aC = ((lane >> 4) & 1) * 4;
    const int bR = ((lane >> 4) & 1) * 8 + r8;
    const int bC = ((lane >> 3) & 1) * 4;
    const int vR = ((lane >> 3) & 1) * 8 + r8;
    const int vC = ((lane >> 4) & 1) * 4;
    const uint32_t smB = (uint32_t)__cvta_generic_to_shared(sma);

    const uint32_t* kh = g_khi + (size_t)bh * S_ * 32;
    const uint32_t* vh = g_vhi + (size_t)bh * S_ * 32;

    const int nkt = (qbase + 128) / 64;

    attn_stage_load(sma, 0, kh, vh, 0, tid);
    cp_commit();

    {
        const uint32_t* qgh = g_qhi + ((size_t)bh * S_ + qbase) * 32;
        for (int idx = tid; idx < 1024; idx += 256) {
            int r = idx >> 3, c4 = (idx & 7) * 4;
            *(uint4*)&sPh[r * APS + c4] = *(const uint4*)(qgh + r * 32 + c4);
        }
        for (int idx = tid; idx < S_; idx += 256)
            sMf[idx] = (amask[b * S_ + idx] == 0) ? -INFINITY : 0.f;
    }
    __syncthreads();

    uint32_t Qh[4][4];
    #pragma unroll
    for (int ks = 0; ks < 4; ks++) {
        const uint32_t qaddr = smB + (((wrow + aR) * APS + ks * 8 + aC) << 2);
        ldsm4(Qh[ks], qaddr);
    }

    float oacc[8][4];
    #pragma unroll
    for (int nt = 0; nt < 8; nt++)
        #pragma unroll
        for (int r = 0; r < 4; r++) oacc[nt][r] = 0.f;
    float mrun[2] = {-INFINITY, -INFINITY};
    float lrun[2] = {0.f, 0.f};

    for (int kt = 0; kt < nkt; kt++) {
        if (kt + 1 < nkt) {
            attn_stage_load(sma, (kt + 1) & 1, kh, vh, kt + 1, tid);
            cp_commit();
            cp_wait<1>();
        } else {
            cp_wait<0>();
        }
        __syncthreads();

        if (kt * 64 <= qbase + wrow + 15) {
            const uint32_t kvB = smB + ((A_KV + (kt & 1) * KV_STAGE) << 2);

            // ---- S = Q K^T  (single hi pass) ----
            float sacc[8][4];
            #pragma unroll
            for (int nt = 0; nt < 8; nt++)
                #pragma unroll
                for (int r = 0; r < 4; r++) sacc[nt][r] = 0.f;

            #pragma unroll
            for (int ks = 0; ks < 4; ks++) {
                uint32_t bb[4][4];
                #pragma unroll
                for (int ntp = 0; ntp < 4; ntp++)
                    ldsm4(bb[ntp], kvB + ((KV_KH + (ntp * 16 + bR) * APS + ks * 8 + bC) << 2));
                #pragma unroll
                for (int ntp = 0; ntp < 4; ntp++) {
                    mma_f16(sacc[2 * ntp],     Qh[ks], bb[ntp]);
                    mma_f16(sacc[2 * ntp + 1], Qh[ks], bb[ntp] + 2);
                }
            }

            // ---- masks + row max (log2 domain) ----
            const bool diag = (kt * 64 + 63) > (qbase + wrow);
            float tmax[2] = {-INFINITY, -INFINITY};
            #pragma unroll
            for (int nt = 0; nt < 8; nt++) {
                #pragma unroll
                for (int e = 0; e < 4; e++) {
                    const int colL = nt * 8 + t * 2 + (e & 1);
                    float v = sacc[nt][e] + sMf[kt * 64 + colL];
                    if (diag) {
                        const int row = qbase + wrow + g + ((e >> 1) << 3);
                        const int col = kt * 64 + colL;
                        if (col > row) v = -INFINITY;
                    }
                    sacc[nt][e] = v;
                    tmax[e >> 1] = fmaxf(tmax[e >> 1], v);
                }
            }
            #pragma unroll
            for (int i = 0; i < 2; i++) {
                tmax[i] = fmaxf(tmax[i], __shfl_xor_sync(0xffffffff, tmax[i], 1));
                tmax[i] = fmaxf(tmax[i], __shfl_xor_sync(0xffffffff, tmax[i], 2));
            }

            // ---- online softmax (base-2); pack P-hi frags IN REGISTERS over sacc ----
            float corr[2], psum[2] = {0.f, 0.f};
            #pragma unroll
            for (int i = 0; i < 2; i++) {
                float mnew = fmaxf(mrun[i], tmax[i]);
                corr[i] = fexp2(mrun[i] - mnew);
                mrun[i] = mnew;
                lrun[i] *= corr[i];
            }
            #pragma unroll
            for (int nt = 0; nt < 8; nt++) {
                oacc[nt][0] *= corr[0]; oacc[nt][1] *= corr[0];
                oacc[nt][2] *= corr[1]; oacc[nt][3] *= corr[1];
            }
            #pragma unroll
            for (int nt = 0; nt < 8; nt++) {
                #pragma unroll
                for (int half = 0; half < 2; half++) {
                    float p0 = fexp2(sacc[nt][half * 2 + 0] - mrun[half]);
                    float p1 = fexp2(sacc[nt][half * 2 + 1] - mrun[half]);
                    psum[half] += p0 + p1;
                    sacc[nt][half * 2] = __uint_as_float(packh(p0, p1));
                }
            }
            #pragma unroll
            for (int i = 0; i < 2; i++) {
                psum[i] += __shfl_xor_sync(0xffffffff, psum[i], 1);
                psum[i] += __shfl_xor_sync(0xffffffff, psum[i], 2);
                lrun[i] += psum[i];
            }

            // ---- O += P V  (P-hi frags from registers; V trans frags) ----
            #pragma unroll
            for (int ks = 0; ks < 4; ks++) {
                uint32_t ph4[4];
                ph4[0] = __float_as_uint(sacc[2 * ks][0]);
                ph4[1] = __float_as_uint(sacc[2 * ks][2]);
                ph4[2] = __float_as_uint(sacc[2 * ks + 1][0]);
                ph4[3] = __float_as_uint(sacc[2 * ks + 1][2]);
                uint32_t vv[4][4];
                #pragma unroll
                for (int ntp = 0; ntp < 4; ntp++)
                    ldsm4t(vv[ntp], kvB + ((KV_VH + (ks * 16 + vR) * APS + ntp * 8 + vC) << 2));
                #pragma unroll
                for (int ntp = 0; ntp < 4; ntp++) {
                    mma_f16(oacc[2 * ntp],     ph4, vv[ntp]);
                    mma_f16(oacc[2 * ntp + 1], ph4, vv[ntp] + 2);
                }
            }
        }
        __syncthreads();
    }

    // ---- epilogue: o/l, fp16 split, packed write ----
    const float inv0 = 1.f / lrun[0];
    const float inv1 = 1.f / lrun[1];
    const int r0 = qbase + wrow + g;
    const int r1 = r0 + 8;
    #pragma unroll
    for (int nt = 0; nt < 8; nt++) {
        float v0 = oacc[nt][0] * inv0, v1 = oacc[nt][1] * inv0;
        float v2 = oacc[nt][2] * inv1, v3 = oacc[nt][3] * inv1;
        const size_t o0 = (size_t)(b * S_ + r0) * 512 + h * 32 + nt * 4 + t;
        const size_t o1 = (size_t)(b * S_ + r1) * 512 + h * 32 + nt * 4 + t;
        float h0 = hhi(v0), h1 = hhi(v1), h2 = hhi(v2), h3 = hhi(v3);
        g_yhi[o0] = packh(h0, h1);
        g_ylo[o0] = packh(v0 - h0, v1 - h1);
        g_yhi[o1] = packh(h2, h3);
        g_ylo[o1] = packh(v2 - h2, v3 - h3);
    }
}

// ---------------- launch ----------------
extern "C" void kernel_launch(void* const* d_in, const int* in_sizes, int n_in,
                              void* d_out, int out_size)
{
    const float* x     = (const float*)d_in[0];
    const float* w_qkv = (const float*)d_in[1];
    const float* w_o   = (const float*)d_in[2];
    const int*   amask = (const int*)d_in[3];
    float* out = (float*)d_out;

    uint32_t *xhi, *xlo, *wqh, *woh, *yhi, *ylo;
    cudaGetSymbolAddress((void**)&xhi, g_xhi);
    cudaGetSymbolAddress((void**)&xlo, g_xlo);
    cudaGetSymbolAddress((void**)&wqh, g_wqh);
    cudaGetSymbolAddress((void**)&woh, g_woh);
    cudaGetSymbolAddress((void**)&yhi, g_yhi);
    cudaGetSymbolAddress((void**)&ylo, g_ylo);

    const int smem_gemm = SMEM_GEMM_U32 * 4;
    cudaFuncSetAttribute(qkv_gemm_rope_kernel,
                         cudaFuncAttributeMaxDynamicSharedMemorySize, smem_gemm);
    cudaFuncSetAttribute(f16_gemm_kernel,
                         cudaFuncAttributeMaxDynamicSharedMemorySize, smem_gemm);
    const int smem_attn = SMEM_ATTN_U32 * 4;
    cudaFuncSetAttribute(attn_tc_kernel,
                         cudaFuncAttributeMaxDynamicSharedMemorySize, smem_attn);

    rope_table_kernel<<<256, 256>>>();

    split2_kernel<<<(B_*S_*D_/2 + 255) / 256, 256>>>(x, xhi, xlo, B_*S_*D_/2);
    wsplit_t_kernel<<<dim3(3*D_/32, D_/32), 256>>>(w_qkv, wqh, D_, 3*D_);
    wsplit_t_kernel<<<dim3(D_/32, D_/32), 256>>>(w_o, woh, D_, D_);

    // QKV = x @ w_qkv with fused RoPE + quantize epilogue
    qkv_gemm_rope_kernel<<<dim3(3*D_/128, B_*S_/128), 256, smem_gemm>>>(xhi, xlo, wqh);

    attn_tc_kernel<<<(S_/128) * B_ * H_, 256, smem_attn>>>(amask);

    // out = y @ w_o
    f16_gemm_kernel<<<dim3(D_/128, B_*S_/128), 256, smem_gemm>>>(
        yhi, ylo, woh, out, B_*S_, D_, D_);
}

// round 15
// speedup vs baseline: 1.4108x; 1.2371x over previous
#include <cuda_runtime.h>
#include <cuda_fp16.h>
#include <math.h>
#include <stdint.h>

#define B_  2
#define S_  2048
#define D_  1024
#define H_  16
#define HD  64

// ---------------- scratch (device globals) ----------------
__device__ float g_cos[S_*32];
__device__ float g_sin[S_*32];
// fp16 packed pairs-along-K as uint32. y: hi+lo. x/weights/Q/K/V: hi only.
__device__ uint32_t g_xhi[B_*S_*D_/2];
__device__ uint32_t g_wqh[3*D_*D_/2];                       // transposed [N][K]
__device__ uint32_t g_woh[D_*D_/2];                         // transposed [N][K]
__device__ uint32_t g_qhi[B_*H_*S_*HD/2];
__device__ uint32_t g_khi[B_*H_*S_*HD/2];
__device__ uint32_t g_vhi[B_*H_*S_*HD/2];                   // V in K-layout [s][d]
__device__ uint32_t g_yhi[B_*S_*D_/2],  g_ylo[B_*S_*D_/2];

// ---------------- helpers ----------------
__device__ __forceinline__ float hhi(float v) {
    return __half2float(__float2half_rn(v));
}
__device__ __forceinline__ uint32_t packh(float f_low, float f_high) {
    uint32_t r;
    asm("cvt.rn.f16x2.f32 %0, %1, %2;" : "=r"(r) : "f"(f_high), "f"(f_low));
    return r;
}
__device__ __forceinline__ float fexp2(float x) {
    float r;
    asm("ex2.approx.f32 %0, %1;" : "=f"(r) : "f"(x));
    return r;
}
__device__ __forceinline__ void cp16(void* dst, const void* src) {
    uint32_t d = (uint32_t)__cvta_generic_to_shared(dst);
    asm volatile("cp.async.cg.shared.global [%0], [%1], 16;\n" :: "r"(d), "l"(src));
}
__device__ __forceinline__ void cp_commit() {
    asm volatile("cp.async.commit_group;\n");
}
template<int N> __device__ __forceinline__ void cp_wait() {
    asm volatile("cp.async.wait_group %0;\n" :: "n"(N));
}
__device__ __forceinline__ void mma_f16(float* d, const uint32_t* a, const uint32_t* b) {
    asm volatile(
        "mma.sync.aligned.m16n8k16.row.col.f32.f16.f16.f32 "
        "{%0,%1,%2,%3}, {%4,%5,%6,%7}, {%8,%9}, {%0,%1,%2,%3};\n"
        : "+f"(d[0]), "+f"(d[1]), "+f"(d[2]), "+f"(d[3])
        : "r"(a[0]), "r"(a[1]), "r"(a[2]), "r"(a[3]), "r"(b[0]), "r"(b[1]));
}
__device__ __forceinline__ void ldsm4(uint32_t* r, uint32_t saddr) {
    asm volatile("ldmatrix.sync.aligned.m8n8.x4.shared.b16 {%0,%1,%2,%3}, [%4];"
        : "=r"(r[0]), "=r"(r[1]), "=r"(r[2]), "=r"(r[3]) : "r"(saddr));
}
__device__ __forceinline__ void ldsm4t(uint32_t* r, uint32_t saddr) {
    asm volatile("ldmatrix.sync.aligned.m8n8.x4.trans.shared.b16 {%0,%1,%2,%3}, [%4];"
        : "=r"(r[0]), "=r"(r[1]), "=r"(r[2]), "=r"(r[3]) : "r"(saddr));
}

#define QSC_ (0.125f * 1.44269504088896340736f)   // 1/sqrt(64) * log2(e)

// ---------------- RoPE table ----------------
__global__ void rope_table_kernel() {
    int idx = blockIdx.x * 256 + threadIdx.x;
    if (idx >= S_ * 32) return;
    int s = idx >> 5;
    int j = idx & 31;
    double inv = pow(10000.0, -((double)(2 * j)) / 64.0);
    double ang = (double)s * inv;
    g_cos[idx] = (float)cos(ang);
    g_sin[idx] = (float)sin(ang);
}

// ---------------- elementwise fp16 quantize (packed pairs, hi only) ----------------
__global__ __launch_bounds__(256) void quant2_kernel(
    const float* __restrict__ src, uint32_t* __restrict__ hi, int n2)
{
    int i = blockIdx.x * 256 + threadIdx.x;
    if (i >= n2) return;
    float2 v = ((const float2*)src)[i];
    hi[i] = packh(v.x, v.y);
}

// ---------------- weight transpose + fp16 quantize: w[K][N] -> wt[N][K] ----------------
__global__ __launch_bounds__(256) void wsplit_t_kernel(
    const float* __restrict__ w, uint32_t* __restrict__ th, int Kd, int Nd)
{
    __shared__ float tile[32][33];
    int n0 = blockIdx.x * 32, k0 = blockIdx.y * 32;
    int tx = threadIdx.x & 31, ty = threadIdx.x >> 5;
    #pragma unroll
    for (int r = 0; r < 32; r += 8)
        tile[ty + r][tx] = w[(size_t)(k0 + ty + r) * Nd + n0 + tx];
    __syncthreads();
    __half* thb = (__half*)th;
    #pragma unroll
    for (int r = 0; r < 32; r += 8) {
        int n = n0 + ty + r, k = k0 + tx;
        thb[(size_t)n * Kd + k] = __float2half_rn(tile[tx][ty + r]);
    }
}

// ---------------- shared GEMM plumbing ----------------
#define KS 20
#define G_AH 0
#define G_AL 2560
#define G_BH 5120
#define G_STAGE 7680
#define SMEM_GEMM_U32 (3*G_STAGE)

template<bool HASLO>
__device__ __forceinline__ void gemm_stage_load(
    uint32_t* st, const uint32_t* Ah, const uint32_t* Al, const uint32_t* Bh,
    int kp0, int tid, int Kp)
{
    const int row = tid >> 1;
    const int c = (tid & 1) * 8;
    const size_t ga = (size_t)row * Kp + kp0 + c;
    cp16(&st[G_AH + row * KS + c],     Ah + ga);
    cp16(&st[G_AH + row * KS + c + 4], Ah + ga + 4);
    if (HASLO) {
        cp16(&st[G_AL + row * KS + c],     Al + ga);
        cp16(&st[G_AL + row * KS + c + 4], Al + ga + 4);
    }
    cp16(&st[G_BH + row * KS + c],     Bh + ga);
    cp16(&st[G_BH + row * KS + c + 4], Bh + ga + 4);
}

// mainloop: hi pass (and optional lo pass) so dependent-acc MMAs sit far apart
#define GEMM_MAINLOOP(ACC, HASLO)                                                       \
    const int NT = Kp / 16;                                                             \
    gemm_stage_load<HASLO>(smg, Ahi, Alo, Bhi, 0, tid, Kp);                             \
    cp_commit();                                                                        \
    gemm_stage_load<HASLO>(smg + G_STAGE, Ahi, Alo, Bhi, 16, tid, Kp);                  \
    cp_commit();                                                                        \
    int stage = 0;                                                                      \
    for (int it = 0; it < NT; it++) {                                                   \
        cp_wait<1>();                                                                   \
        __syncthreads();                                                                \
        if (it + 2 < NT) {                                                              \
            int s2 = stage + 2; if (s2 >= 3) s2 -= 3;                                   \
            gemm_stage_load<HASLO>(smg + s2 * G_STAGE, Ahi, Alo, Bhi, (it + 2) * 16, tid, Kp); \
        }                                                                               \
        cp_commit();                                                                    \
        const uint32_t stB = smB + (stage * G_STAGE) * 4;                               \
        _Pragma("unroll")                                                               \
        for (int kstep = 0; kstep < 2; kstep++) {                                       \
            const int k8 = kstep * 8;                                                   \
            uint32_t ah[2][4], al[2][4];                                                \
            _Pragma("unroll")                                                           \
            for (int mt = 0; mt < 2; mt++) {                                            \
                const uint32_t ab = stB + ((G_AH + (mBase + mt*16 + aR)*KS + k8 + aC) << 2); \
                ldsm4(ah[mt], ab);                                                      \
                if (HASLO) ldsm4(al[mt], ab + (G_AL - G_AH) * 4);                       \
            }                                                                           \
            uint32_t bb[4][4];                                                          \
            _Pragma("unroll")                                                           \
            for (int ntp = 0; ntp < 4; ntp++)                                           \
                ldsm4(bb[ntp], stB + ((G_BH + (nBase + ntp*16 + bR)*KS + k8 + bC) << 2)); \
            _Pragma("unroll")                                                           \
            for (int ntp = 0; ntp < 4; ntp++)                                           \
                _Pragma("unroll")                                                       \
                for (int mt = 0; mt < 2; mt++) {                                        \
                    mma_f16(ACC[mt][2*ntp],     ah[mt], bb[ntp]);                       \
                    mma_f16(ACC[mt][2*ntp + 1], ah[mt], bb[ntp] + 2);                   \
                }                                                                       \
            if (HASLO) {                                                                \
                _Pragma("unroll")                                                       \
                for (int ntp = 0; ntp < 4; ntp++)                                       \
                    _Pragma("unroll")                                                   \
                    for (int mt = 0; mt < 2; mt++) {                                    \
                        mma_f16(ACC[mt][2*ntp],     al[mt], bb[ntp]);                   \
                        mma_f16(ACC[mt][2*ntp + 1], al[mt], bb[ntp] + 2);               \
                    }                                                                   \
            }                                                                           \
        }                                                                               \
        if (++stage == 3) stage = 0;                                                    \
    }

// ---------------- QKV GEMM (A hi-only) with fused RoPE + fp16 quantize epilogue ----------------
__global__ __launch_bounds__(256, 2) void qkv_gemm_rope_kernel(
    const uint32_t* __restrict__ Ahi, const uint32_t* __restrict__ Bhi)
{
    extern __shared__ uint32_t smg[];
    const int Kp = D_ >> 1;
    const int tid  = threadIdx.x;
    const int warp = tid >> 5;
    const int lane = tid & 31;
    const int g = lane >> 2;
    const int t = lane & 3;
    const int mBase = (warp >> 1) * 32;
    const int nBase = (warp & 1) * 64;

    const int r8 = lane & 7;
    const int aR = ((lane >> 3) & 1) * 8 + r8;
    const int aC = ((lane >> 4) & 1) * 4;
    const int bR = ((lane >> 4) & 1) * 8 + r8;
    const int bC = ((lane >> 3) & 1) * 4;
    const uint32_t smB = (uint32_t)__cvta_generic_to_shared(smg);

    Ahi += (size_t)blockIdx.y * 128 * Kp;
    const uint32_t* Alo = Ahi;   // unused (HASLO=false)
    Bhi += (size_t)blockIdx.x * 128 * Kp;

    float acc[2][8][4];
    #pragma unroll
    for (int mt = 0; mt < 2; mt++)
        #pragma unroll
        for (int nt = 0; nt < 8; nt++)
            #pragma unroll
            for (int r = 0; r < 4; r++) acc[mt][nt][r] = 0.f;

    GEMM_MAINLOOP(acc, false)

    // ---- fused epilogue: RoPE (q,k) + fp16 quantize, V passthrough quantize ----
    const int gcolbase = blockIdx.x * 128 + nBase;   // multiple of 64
    const int region = gcolbase >> 10;               // 0=q 1=k 2=v
    const int head   = (gcolbase & 1023) >> 6;

    #pragma unroll
    for (int mt = 0; mt < 2; mt++) {
        #pragma unroll
        for (int rs = 0; rs < 2; rs++) {
            const int m = blockIdx.y * 128 + mBase + mt * 16 + g + rs * 8;
            const int b = m >> 11, s = m & 2047;
            const size_t dbase = ((size_t)(b * 16 + head) * S_ + s) * 32;
            if (region == 2) {
                #pragma unroll
                for (int nt = 0; nt < 8; nt++) {
                    float v0 = acc[mt][nt][rs * 2 + 0];
                    float v1 = acc[mt][nt][rs * 2 + 1];
                    g_vhi[dbase + nt * 4 + t] = packh(v0, v1);
                }
            } else {
                #pragma unroll
                for (int nt = 0; nt < 8; nt++) {
                    const int i0 = nt * 8 + t * 2;
                    const int j0 = i0 & 31;
                    float c0 = g_cos[s * 32 + j0], c1 = g_cos[s * 32 + j0 + 1];
                    float s0 = g_sin[s * 32 + j0], s1 = g_sin[s * 32 + j0 + 1];
                    float sg = (i0 < 32) ? -1.f : 1.f;
                    float v0 = acc[mt][nt][rs * 2 + 0];
                    float v1 = acc[mt][nt][rs * 2 + 1];
                    float p0 = acc[mt][nt ^ 4][rs * 2 + 0];
                    float p1 = acc[mt][nt ^ 4][rs * 2 + 1];
                    float r0 = v0 * c0 + sg * p0 * s0;
                    float r1 = v1 * c1 + sg * p1 * s1;
                    if (region == 0) {
                        g_qhi[dbase + nt * 4 + t] = packh(r0 * QSC_, r1 * QSC_);
                    } else {
                        g_khi[dbase + nt * 4 + t] = packh(r0, r1);
                    }
                }
            }
        }
    }
}

// ---------------- O-proj fp16 2-product GEMM (A = y hi+lo) ----------------
__global__ __launch_bounds__(256, 2) void f16_gemm_kernel(
    const uint32_t* __restrict__ Ahi, const uint32_t* __restrict__ Alo,
    const uint32_t* __restrict__ Bhi,
    float* __restrict__ C, int M, int N, int K)
{
    extern __shared__ uint32_t smg[];
    const int Kp = K >> 1;
    const int tid  = threadIdx.x;
    const int warp = tid >> 5;
    const int lane = tid & 31;
    const int g = lane >> 2;
    const int t = lane & 3;
    const int mBase = (warp >> 1) * 32;
    const int nBase = (warp & 1) * 64;

    const int r8 = lane & 7;
    const int aR = ((lane >> 3) & 1) * 8 + r8;
    const int aC = ((lane >> 4) & 1) * 4;
    const int bR = ((lane >> 4) & 1) * 8 + r8;
    const int bC = ((lane >> 3) & 1) * 4;
    const uint32_t smB = (uint32_t)__cvta_generic_to_shared(smg);

    Ahi += (size_t)blockIdx.y * 128 * Kp;
    Alo += (size_t)blockIdx.y * 128 * Kp;
    Bhi += (size_t)blockIdx.x * 128 * Kp;

    float acc[2][8][4];
    #pragma unroll
    for (int mt = 0; mt < 2; mt++)
        #pragma unroll
        for (int nt = 0; nt < 8; nt++)
            #pragma unroll
            for (int r = 0; r < 4; r++) acc[mt][nt][r] = 0.f;

    GEMM_MAINLOOP(acc, true)

    C += (size_t)blockIdx.y * 128 * N + blockIdx.x * 128;
    #pragma unroll
    for (int mt = 0; mt < 2; mt++) {
        const int r0 = mBase + mt * 16 + g;
        #pragma unroll
        for (int nt = 0; nt < 8; nt++) {
            const int c = nBase + nt * 8 + t * 2;
            *(float2*)&C[(size_t)r0 * N + c]       = make_float2(acc[mt][nt][0], acc[mt][nt][1]);
            *(float2*)&C[(size_t)(r0 + 8) * N + c] = make_float2(acc[mt][nt][2], acc[mt][nt][3]);
        }
    }
}

// ---------------- fp16 tensor-core causal flash attention ----------------
#define APS 36
#define A_PH 0
#define A_KV 4608
#define KV_KH 0
#define KV_VH 2304
#define KV_STAGE 4608
#define A_MSK (A_KV + 2*KV_STAGE)
#define SMEM_ATTN_U32 (A_MSK + S_)

__device__ __forceinline__ void attn_stage_load(
    uint32_t* sma, int st, const uint32_t* kh, const uint32_t* vh, int kt, int tid)
{
    uint32_t* base = sma + A_KV + st * KV_STAGE;
    const int r = tid >> 2, c = tid & 3;
    const size_t gk = (size_t)(kt * 64 + r) * 32;
    cp16(&base[KV_KH + r * APS + c * 4],       kh + gk + c * 4);
    cp16(&base[KV_KH + r * APS + (c + 4) * 4], kh + gk + (c + 4) * 4);
    cp16(&base[KV_VH + r * APS + c * 4],       vh + gk + c * 4);
    cp16(&base[KV_VH + r * APS + (c + 4) * 4], vh + gk + (c + 4) * 4);
}

__global__ __launch_bounds__(256, 2) void attn_tc_kernel(const int* __restrict__ amask) {
    extern __shared__ uint32_t sma[];
    uint32_t* sPh = sma + A_PH;
    float* sMf = (float*)(sma + A_MSK);

    const int tid  = threadIdx.x;
    const int warp = tid >> 5;
    const int lane = tid & 31;
    const int g = lane >> 2;
    const int t = lane & 3;
    // LPT ordering: heaviest q-tiles first
    const int qtile = (S_ / 128 - 1) - (int)(blockIdx.x >> 5);
    const int bh    = blockIdx.x & 31;
    const int b  = bh >> 4;
    const int h  = bh & 15;
    const int qbase = qtile * 128;
    const int wrow  = warp * 16;

    const int r8 = lane & 7;
    const int aR = ((lane >> 3) & 1) * 8 + r8;
    const int aC = ((lane >> 4) & 1) * 4;
    const int bR = ((lane >> 4) & 1) * 8 + r8;
    const int bC = ((lane >> 3) & 1) * 4;
    const int vR = ((lane >> 3) & 1) * 8 + r8;
    const int vC = ((lane >> 4) & 1) * 4;
    const uint32_t smB = (uint32_t)__cvta_generic_to_shared(sma);

    const uint32_t* kh = g_khi + (size_t)bh * S_ * 32;
    const uint32_t* vh = g_vhi + (size_t)bh * S_ * 32;

    const int nkt = (qbase + 128) / 64;

    attn_stage_load(sma, 0, kh, vh, 0, tid);
    cp_commit();

    {
        const uint32_t* qgh = g_qhi + ((size_t)bh * S_ + qbase) * 32;
        for (int idx = tid; idx < 1024; idx += 256) {
            int r = idx >> 3, c4 = (idx & 7) * 4;
            *(uint4*)&sPh[r * APS + c4] = *(const uint4*)(qgh + r * 32 + c4);
        }
        for (int idx = tid; idx < S_; idx += 256)
            sMf[idx] = (amask[b * S_ + idx] == 0) ? -INFINITY : 0.f;
    }
    __syncthreads();

    uint32_t Qh[4][4];
    #pragma unroll
    for (int ks = 0; ks < 4; ks++) {
        const uint32_t qaddr = smB + (((wrow + aR) * APS + ks * 8 + aC) << 2);
        ldsm4(Qh[ks], qaddr);
    }

    float oacc[8][4];
    #pragma unroll
    for (int nt = 0; nt < 8; nt++)
        #pragma unroll
        for (int r = 0; r < 4; r++) oacc[nt][r] = 0.f;
    float mrun[2] = {-INFINITY, -INFINITY};
    float lrun[2] = {0.f, 0.f};

    for (int kt = 0; kt < nkt; kt++) {
        if (kt + 1 < nkt) {
            attn_stage_load(sma, (kt + 1) & 1, kh, vh, kt + 1, tid);
            cp_commit();
            cp_wait<1>();
        } else {
            cp_wait<0>();
        }
        __syncthreads();

        if (kt * 64 <= qbase + wrow + 15) {
            const uint32_t kvB = smB + ((A_KV + (kt & 1) * KV_STAGE) << 2);

            // ---- S = Q K^T  (single hi pass) ----
            float sacc[8][4];
            #pragma unroll
            for (int nt = 0; nt < 8; nt++)
                #pragma unroll
                for (int r = 0; r < 4; r++) sacc[nt][r] = 0.f;

            #pragma unroll
            for (int ks = 0; ks < 4; ks++) {
                uint32_t bb[4][4];
                #pragma unroll
                for (int ntp = 0; ntp < 4; ntp++)
                    ldsm4(bb[ntp], kvB + ((KV_KH + (ntp * 16 + bR) * APS + ks * 8 + bC) << 2));
                #pragma unroll
                for (int ntp = 0; ntp < 4; ntp++) {
                    mma_f16(sacc[2 * ntp],     Qh[ks], bb[ntp]);
                    mma_f16(sacc[2 * ntp + 1], Qh[ks], bb[ntp] + 2);
                }
            }

            // ---- masks + row max (log2 domain) ----
            const bool diag = (kt * 64 + 63) > (qbase + wrow);
            float tmax[2] = {-INFINITY, -INFINITY};
            #pragma unroll
            for (int nt = 0; nt < 8; nt++) {
                #pragma unroll
                for (int e = 0; e < 4; e++) {
                    const int colL = nt * 8 + t * 2 + (e & 1);
                    float v = sacc[nt][e] + sMf[kt * 64 + colL];
                    if (diag) {
                        const int row = qbase + wrow + g + ((e >> 1) << 3);
                        const int col = kt * 64 + colL;
                        if (col > row) v = -INFINITY;
                    }
                    sacc[nt][e] = v;
                    tmax[e >> 1] = fmaxf(tmax[e >> 1], v);
                }
            }
            #pragma unroll
            for (int i = 0; i < 2; i++) {
                tmax[i] = fmaxf(tmax[i], __shfl_xor_sync(0xffffffff, tmax[i], 1));
                tmax[i] = fmaxf(tmax[i], __shfl_xor_sync(0xffffffff, tmax[i], 2));
            }

            // ---- online softmax (base-2); pack P-hi frags IN REGISTERS over sacc ----
            float corr[2], psum[2] = {0.f, 0.f};
            #pragma unroll
            for (int i = 0; i < 2; i++) {
                float mnew = fmaxf(mrun[i], tmax[i]);
                corr[i] = fexp2(mrun[i] - mnew);
                mrun[i] = mnew;
                lrun[i] *= corr[i];
            }
            #pragma unroll
            for (int nt = 0; nt < 8; nt++) {
                oacc[nt][0] *= corr[0]; oacc[nt][1] *= corr[0];
                oacc[nt][2] *= corr[1]; oacc[nt][3] *= corr[1];
            }
            #pragma unroll
            for (int nt = 0; nt < 8; nt++) {
                #pragma unroll
                for (int half = 0; half < 2; half++) {
                    float p0 = fexp2(sacc[nt][half * 2 + 0] - mrun[half]);
                    float p1 = fexp2(sacc[nt][half * 2 + 1] - mrun[half]);
                    psum[half] += p0 + p1;
                    sacc[nt][half * 2] = __uint_as_float(packh(p0, p1));
                }
            }
            #pragma unroll
            for (int i = 0; i < 2; i++) {
                psum[i] += __shfl_xor_sync(0xffffffff, psum[i], 1);
                psum[i] += __shfl_xor_sync(0xffffffff, psum[i], 2);
                lrun[i] += psum[i];
            }

            // ---- O += P V  (P-hi frags from registers; V trans frags) ----
            #pragma unroll
            for (int ks = 0; ks < 4; ks++) {
                uint32_t ph4[4];
                ph4[0] = __float_as_uint(sacc[2 * ks][0]);
                ph4[1] = __float_as_uint(sacc[2 * ks][2]);
                ph4[2] = __float_as_uint(sacc[2 * ks + 1][0]);
                ph4[3] = __float_as_uint(sacc[2 * ks + 1][2]);
                uint32_t vv[4][4];
                #pragma unroll
                for (int ntp = 0; ntp < 4; ntp++)
                    ldsm4t(vv[ntp], kvB + ((KV_VH + (ks * 16 + vR) * APS + ntp * 8 + vC) << 2));
                #pragma unroll
                for (int ntp = 0; ntp < 4; ntp++) {
                    mma_f16(oacc[2 * ntp],     ph4, vv[ntp]);
                    mma_f16(oacc[2 * ntp + 1], ph4, vv[ntp] + 2);
                }
            }
        }
        __syncthreads();
    }

    // ---- epilogue: o/l, fp16 split, packed write ----
    const float inv0 = 1.f / lrun[0];
    const float inv1 = 1.f / lrun[1];
    const int r0 = qbase + wrow + g;
    const int r1 = r0 + 8;
    #pragma unroll
    for (int nt = 0; nt < 8; nt++) {
        float v0 = oacc[nt][0] * inv0, v1 = oacc[nt][1] * inv0;
        float v2 = oacc[nt][2] * inv1, v3 = oacc[nt][3] * inv1;
        const size_t o0 = (size_t)(b * S_ + r0) * 512 + h * 32 + nt * 4 + t;
        const size_t o1 = (size_t)(b * S_ + r1) * 512 + h * 32 + nt * 4 + t;
        float h0 = hhi(v0), h1 = hhi(v1), h2 = hhi(v2), h3 = hhi(v3);
        g_yhi[o0] = packh(h0, h1);
        g_ylo[o0] = packh(v0 - h0, v1 - h1);
        g_yhi[o1] = packh(h2, h3);
        g_ylo[o1] = packh(v2 - h2, v3 - h3);
    }
}

// ---------------- launch ----------------
extern "C" void kernel_launch(void* const* d_in, const int* in_sizes, int n_in,
                              void* d_out, int out_size)
{
    const float* x     = (const float*)d_in[0];
    const float* w_qkv = (const float*)d_in[1];
    const float* w_o   = (const float*)d_in[2];
    const int*   amask = (const int*)d_in[3];
    float* out = (float*)d_out;

    uint32_t *xhi, *wqh, *woh, *yhi, *ylo;
    cudaGetSymbolAddress((void**)&xhi, g_xhi);
    cudaGetSymbolAddress((void**)&wqh, g_wqh);
    cudaGetSymbolAddress((void**)&woh, g_woh);
    cudaGetSymbolAddress((void**)&yhi, g_yhi);
    cudaGetSymbolAddress((void**)&ylo, g_ylo);

    const int smem_gemm = SMEM_GEMM_U32 * 4;
    cudaFuncSetAttribute(qkv_gemm_rope_kernel,
                         cudaFuncAttributeMaxDynamicSharedMemorySize, smem_gemm);
    cudaFuncSetAttribute(f16_gemm_kernel,
                         cudaFuncAttributeMaxDynamicSharedMemorySize, smem_gemm);
    const int smem_attn = SMEM_ATTN_U32 * 4;
    cudaFuncSetAttribute(attn_tc_kernel,
                         cudaFuncAttributeMaxDynamicSharedMemorySize, smem_attn);

    rope_table_kernel<<<256, 256>>>();

    quant2_kernel<<<(B_*S_*D_/2 + 255) / 256, 256>>>(x, xhi, B_*S_*D_/2);
    wsplit_t_kernel<<<dim3(3*D_/32, D_/32), 256>>>(w_qkv, wqh, D_, 3*D_);
    wsplit_t_kernel<<<dim3(D_/32, D_/32), 256>>>(w_o, woh, D_, D_);

    // QKV = x @ w_qkv with fused RoPE + quantize epilogue (A hi-only)
    qkv_gemm_rope_kernel<<<dim3(3*D_/128, B_*S_/128), 256, smem_gemm>>>(xhi, wqh);

    attn_tc_kernel<<<(S_/128) * B_ * H_, 256, smem_attn>>>(amask);

    // out = y @ w_o  (y hi+lo protects final output)
    f16_gemm_kernel<<<dim3(D_/128, B_*S_/128), 256, smem_gemm>>>(
        yhi, ylo, woh, out, B_*S_, D_, D_);
}

// round 16
// speedup vs baseline: 1.5382x; 1.0903x over previous
#include <cuda_runtime.h>
#include <cuda_fp16.h>
#include <math.h>
#include <stdint.h>

#define B_  2
#define S_  2048
#define D_  1024
#define H_  16
#define HD  64

// ---------------- scratch (device globals) ----------------
__device__ float g_cos[S_*32];
__device__ float g_sin[S_*32];
// fp16 packed pairs-along-K as uint32, all hi-only.
__device__ uint32_t g_xhi[B_*S_*D_/2];
__device__ uint32_t g_wqh[3*D_*D_/2];                       // transposed [N][K]
__device__ uint32_t g_woh[D_*D_/2];                         // transposed [N][K]
__device__ uint32_t g_qhi[B_*H_*S_*HD/2];
__device__ uint32_t g_khi[B_*H_*S_*HD/2];
__device__ uint32_t g_vhi[B_*H_*S_*HD/2];                   // V in K-layout [s][d]
__device__ uint32_t g_yhi[B_*S_*D_/2];

// ---------------- helpers ----------------
__device__ __forceinline__ float hhi(float v) {
    return __half2float(__float2half_rn(v));
}
__device__ __forceinline__ uint32_t packh(float f_low, float f_high) {
    uint32_t r;
    asm("cvt.rn.f16x2.f32 %0, %1, %2;" : "=r"(r) : "f"(f_high), "f"(f_low));
    return r;
}
__device__ __forceinline__ float fexp2(float x) {
    float r;
    asm("ex2.approx.f32 %0, %1;" : "=f"(r) : "f"(x));
    return r;
}
__device__ __forceinline__ void cp16(void* dst, const void* src) {
    uint32_t d = (uint32_t)__cvta_generic_to_shared(dst);
    asm volatile("cp.async.cg.shared.global [%0], [%1], 16;\n" :: "r"(d), "l"(src));
}
__device__ __forceinline__ void cp_commit() {
    asm volatile("cp.async.commit_group;\n");
}
template<int N> __device__ __forceinline__ void cp_wait() {
    asm volatile("cp.async.wait_group %0;\n" :: "n"(N));
}
__device__ __forceinline__ void mma_f16(float* d, const uint32_t* a, const uint32_t* b) {
    asm volatile(
        "mma.sync.aligned.m16n8k16.row.col.f32.f16.f16.f32 "
        "{%0,%1,%2,%3}, {%4,%5,%6,%7}, {%8,%9}, {%0,%1,%2,%3};\n"
        : "+f"(d[0]), "+f"(d[1]), "+f"(d[2]), "+f"(d[3])
        : "r"(a[0]), "r"(a[1]), "r"(a[2]), "r"(a[3]), "r"(b[0]), "r"(b[1]));
}
__device__ __forceinline__ void ldsm4(uint32_t* r, uint32_t saddr) {
    asm volatile("ldmatrix.sync.aligned.m8n8.x4.shared.b16 {%0,%1,%2,%3}, [%4];"
        : "=r"(r[0]), "=r"(r[1]), "=r"(r[2]), "=r"(r[3]) : "r"(saddr));
}
__device__ __forceinline__ void ldsm4t(uint32_t* r, uint32_t saddr) {
    asm volatile("ldmatrix.sync.aligned.m8n8.x4.trans.shared.b16 {%0,%1,%2,%3}, [%4];"
        : "=r"(r[0]), "=r"(r[1]), "=r"(r[2]), "=r"(r[3]) : "r"(saddr));
}

#define QSC_ (0.125f * 1.44269504088896340736f)   // 1/sqrt(64) * log2(e)

// ---------------- RoPE table ----------------
__global__ void rope_table_kernel() {
    int idx = blockIdx.x * 256 + threadIdx.x;
    if (idx >= S_ * 32) return;
    int s = idx >> 5;
    int j = idx & 31;
    double inv = pow(10000.0, -((double)(2 * j)) / 64.0);
    double ang = (double)s * inv;
    g_cos[idx] = (float)cos(ang);
    g_sin[idx] = (float)sin(ang);
}

// ---------------- elementwise fp16 quantize (packed pairs, hi only) ----------------
__global__ __launch_bounds__(256) void quant2_kernel(
    const float* __restrict__ src, uint32_t* __restrict__ hi, int n2)
{
    int i = blockIdx.x * 256 + threadIdx.x;
    if (i >= n2) return;
    float2 v = ((const float2*)src)[i];
    hi[i] = packh(v.x, v.y);
}

// ---------------- weight transpose + fp16 quantize: w[K][N] -> wt[N][K] ----------------
__global__ __launch_bounds__(256) void wsplit_t_kernel(
    const float* __restrict__ w, uint32_t* __restrict__ th, int Kd, int Nd)
{
    __shared__ float tile[32][33];
    int n0 = blockIdx.x * 32, k0 = blockIdx.y * 32;
    int tx = threadIdx.x & 31, ty = threadIdx.x >> 5;
    #pragma unroll
    for (int r = 0; r < 32; r += 8)
        tile[ty + r][tx] = w[(size_t)(k0 + ty + r) * Nd + n0 + tx];
    __syncthreads();
    __half* thb = (__half*)th;
    #pragma unroll
    for (int r = 0; r < 32; r += 8) {
        int n = n0 + ty + r, k = k0 + tx;
        thb[(size_t)n * Kd + k] = __float2half_rn(tile[tx][ty + r]);
    }
}

// ---------------- shared GEMM plumbing (hi-only) ----------------
#define KS 20
#define G_AH 0
#define G_BH 2560
#define G_STAGE 5120
#define SMEM_GEMM_U32 (3*G_STAGE)

__device__ __forceinline__ void gemm_stage_load(
    uint32_t* st, const uint32_t* Ah, const uint32_t* Bh, int kp0, int tid, int Kp)
{
    const int row = tid >> 1;
    const int c = (tid & 1) * 8;
    const size_t ga = (size_t)row * Kp + kp0 + c;
    cp16(&st[G_AH + row * KS + c],     Ah + ga);
    cp16(&st[G_AH + row * KS + c + 4], Ah + ga + 4);
    cp16(&st[G_BH + row * KS + c],     Bh + ga);
    cp16(&st[G_BH + row * KS + c + 4], Bh + ga + 4);
}

#define GEMM_MAINLOOP(ACC)                                                              \
    const int NT = Kp / 16;                                                             \
    gemm_stage_load(smg, Ahi, Bhi, 0, tid, Kp);                                         \
    cp_commit();                                                                        \
    gemm_stage_load(smg + G_STAGE, Ahi, Bhi, 16, tid, Kp);                              \
    cp_commit();                                                                        \
    int stage = 0;                                                                      \
    for (int it = 0; it < NT; it++) {                                                   \
        cp_wait<1>();                                                                   \
        __syncthreads();                                                                \
        if (it + 2 < NT) {                                                              \
            int s2 = stage + 2; if (s2 >= 3) s2 -= 3;                                   \
            gemm_stage_load(smg + s2 * G_STAGE, Ahi, Bhi, (it + 2) * 16, tid, Kp);      \
        }                                                                               \
        cp_commit();                                                                    \
        const uint32_t stB = smB + (stage * G_STAGE) * 4;                               \
        _Pragma("unroll")                                                               \
        for (int kstep = 0; kstep < 2; kstep++) {                                       \
            const int k8 = kstep * 8;                                                   \
            uint32_t ah[2][4];                                                          \
            _Pragma("unroll")                                                           \
            for (int mt = 0; mt < 2; mt++)                                              \
                ldsm4(ah[mt], stB + ((G_AH + (mBase + mt*16 + aR)*KS + k8 + aC) << 2)); \
            uint32_t bb[4][4];                                                          \
            _Pragma("unroll")                                                           \
            for (int ntp = 0; ntp < 4; ntp++)                                           \
                ldsm4(bb[ntp], stB + ((G_BH + (nBase + ntp*16 + bR)*KS + k8 + bC) << 2)); \
            _Pragma("unroll")                                                           \
            for (int ntp = 0; ntp < 4; ntp++)                                           \
                _Pragma("unroll")                                                       \
                for (int mt = 0; mt < 2; mt++) {                                        \
                    mma_f16(ACC[mt][2*ntp],     ah[mt], bb[ntp]);                       \
                    mma_f16(ACC[mt][2*ntp + 1], ah[mt], bb[ntp] + 2);                   \
                }                                                                       \
        }                                                                               \
        if (++stage == 3) stage = 0;                                                    \
    }

// ---------------- QKV GEMM with fused RoPE + fp16 quantize epilogue ----------------
__global__ __launch_bounds__(256, 2) void qkv_gemm_rope_kernel(
    const uint32_t* __restrict__ Ahi, const uint32_t* __restrict__ Bhi)
{
    extern __shared__ uint32_t smg[];
    const int Kp = D_ >> 1;
    const int tid  = threadIdx.x;
    const int warp = tid >> 5;
    const int lane = tid & 31;
    const int g = lane >> 2;
    const int t = lane & 3;
    const int mBase = (warp >> 1) * 32;
    const int nBase = (warp & 1) * 64;

    const int r8 = lane & 7;
    const int aR = ((lane >> 3) & 1) * 8 + r8;
    const int aC = ((lane >> 4) & 1) * 4;
    const int bR = ((lane >> 4) & 1) * 8 + r8;
    const int bC = ((lane >> 3) & 1) * 4;
    const uint32_t smB = (uint32_t)__cvta_generic_to_shared(smg);

    Ahi += (size_t)blockIdx.y * 128 * Kp;
    Bhi += (size_t)blockIdx.x * 128 * Kp;

    float acc[2][8][4];
    #pragma unroll
    for (int mt = 0; mt < 2; mt++)
        #pragma unroll
        for (int nt = 0; nt < 8; nt++)
            #pragma unroll
            for (int r = 0; r < 4; r++) acc[mt][nt][r] = 0.f;

    GEMM_MAINLOOP(acc)

    // ---- fused epilogue: RoPE (q,k) + fp16 quantize, V passthrough quantize ----
    const int gcolbase = blockIdx.x * 128 + nBase;   // multiple of 64
    const int region = gcolbase >> 10;               // 0=q 1=k 2=v
    const int head   = (gcolbase & 1023) >> 6;

    #pragma unroll
    for (int mt = 0; mt < 2; mt++) {
        #pragma unroll
        for (int rs = 0; rs < 2; rs++) {
            const int m = blockIdx.y * 128 + mBase + mt * 16 + g + rs * 8;
            const int b = m >> 11, s = m & 2047;
            const size_t dbase = ((size_t)(b * 16 + head) * S_ + s) * 32;
            if (region == 2) {
                #pragma unroll
                for (int nt = 0; nt < 8; nt++) {
                    g_vhi[dbase + nt * 4 + t] = packh(acc[mt][nt][rs * 2 + 0],
                                                      acc[mt][nt][rs * 2 + 1]);
                }
            } else {
                #pragma unroll
                for (int nt = 0; nt < 8; nt++) {
                    const int i0 = nt * 8 + t * 2;
                    const int j0 = i0 & 31;
                    float c0 = g_cos[s * 32 + j0], c1 = g_cos[s * 32 + j0 + 1];
                    float s0 = g_sin[s * 32 + j0], s1 = g_sin[s * 32 + j0 + 1];
                    float sg = (i0 < 32) ? -1.f : 1.f;
                    float v0 = acc[mt][nt][rs * 2 + 0];
                    float v1 = acc[mt][nt][rs * 2 + 1];
                    float p0 = acc[mt][nt ^ 4][rs * 2 + 0];
                    float p1 = acc[mt][nt ^ 4][rs * 2 + 1];
                    float r0 = v0 * c0 + sg * p0 * s0;
                    float r1 = v1 * c1 + sg * p1 * s1;
                    if (region == 0) {
                        g_qhi[dbase + nt * 4 + t] = packh(r0 * QSC_, r1 * QSC_);
                    } else {
                        g_khi[dbase + nt * 4 + t] = packh(r0, r1);
                    }
                }
            }
        }
    }
}

// ---------------- O-proj fp16 hi-only GEMM ----------------
__global__ __launch_bounds__(256, 2) void f16_gemm_kernel(
    const uint32_t* __restrict__ Ahi, const uint32_t* __restrict__ Bhi,
    float* __restrict__ C, int M, int N, int K)
{
    extern __shared__ uint32_t smg[];
    const int Kp = K >> 1;
    const int tid  = threadIdx.x;
    const int warp = tid >> 5;
    const int lane = tid & 31;
    const int g = lane >> 2;
    const int t = lane & 3;
    const int mBase = (warp >> 1) * 32;
    const int nBase = (warp & 1) * 64;

    const int r8 = lane & 7;
    const int aR = ((lane >> 3) & 1) * 8 + r8;
    const int aC = ((lane >> 4) & 1) * 4;
    const int bR = ((lane >> 4) & 1) * 8 + r8;
    const int bC = ((lane >> 3) & 1) * 4;
    const uint32_t smB = (uint32_t)__cvta_generic_to_shared(smg);

    Ahi += (size_t)blockIdx.y * 128 * Kp;
    Bhi += (size_t)blockIdx.x * 128 * Kp;

    float acc[2][8][4];
    #pragma unroll
    for (int mt = 0; mt < 2; mt++)
        #pragma unroll
        for (int nt = 0; nt < 8; nt++)
            #pragma unroll
            for (int r = 0; r < 4; r++) acc[mt][nt][r] = 0.f;

    GEMM_MAINLOOP(acc)

    C += (size_t)blockIdx.y * 128 * N + blockIdx.x * 128;
    #pragma unroll
    for (int mt = 0; mt < 2; mt++) {
        const int r0 = mBase + mt * 16 + g;
        #pragma unroll
        for (int nt = 0; nt < 8; nt++) {
            const int c = nBase + nt * 8 + t * 2;
            *(float2*)&C[(size_t)r0 * N + c]       = make_float2(acc[mt][nt][0], acc[mt][nt][1]);
            *(float2*)&C[(size_t)(r0 + 8) * N + c] = make_float2(acc[mt][nt][2], acc[mt][nt][3]);
        }
    }
}

// ---------------- fp16 tensor-core causal flash attention ----------------
#define APS 36
#define A_PH 0
#define A_KV 4608
#define KV_KH 0
#define KV_VH 2304
#define KV_STAGE 4608
#define A_MSK (A_KV + 2*KV_STAGE)
#define SMEM_ATTN_U32 (A_MSK + S_)

__device__ __forceinline__ void attn_stage_load(
    uint32_t* sma, int st, const uint32_t* kh, const uint32_t* vh, int kt, int tid)
{
    uint32_t* base = sma + A_KV + st * KV_STAGE;
    const int r = tid >> 2, c = tid & 3;
    const size_t gk = (size_t)(kt * 64 + r) * 32;
    cp16(&base[KV_KH + r * APS + c * 4],       kh + gk + c * 4);
    cp16(&base[KV_KH + r * APS + (c + 4) * 4], kh + gk + (c + 4) * 4);
    cp16(&base[KV_VH + r * APS + c * 4],       vh + gk + c * 4);
    cp16(&base[KV_VH + r * APS + (c + 4) * 4], vh + gk + (c + 4) * 4);
}

__global__ __launch_bounds__(256, 2) void attn_tc_kernel(const int* __restrict__ amask) {
    extern __shared__ uint32_t sma[];
    uint32_t* sPh = sma + A_PH;
    float* sMf = (float*)(sma + A_MSK);

    const int tid  = threadIdx.x;
    const int warp = tid >> 5;
    const int lane = tid & 31;
    const int g = lane >> 2;
    const int t = lane & 3;
    // LPT ordering: heaviest q-tiles first
    const int qtile = (S_ / 128 - 1) - (int)(blockIdx.x >> 5);
    const int bh    = blockIdx.x & 31;
    const int b  = bh >> 4;
    const int h  = bh & 15;
    const int qbase = qtile * 128;
    const int wrow  = warp * 16;

    const int r8 = lane & 7;
    const int aR = ((lane >> 3) & 1) * 8 + r8;
    const int aC = ((lane >> 4) & 1) * 4;
    const int bR = ((lane >> 4) & 1) * 8 + r8;
    const int bC = ((lane >> 3) & 1) * 4;
    const int vR = ((lane >> 3) & 1) * 8 + r8;
    const int vC = ((lane >> 4) & 1) * 4;
    const uint32_t smB = (uint32_t)__cvta_generic_to_shared(sma);

    const uint32_t* kh = g_khi + (size_t)bh * S_ * 32;
    const uint32_t* vh = g_vhi + (size_t)bh * S_ * 32;

    const int nkt = (qbase + 128) / 64;

    attn_stage_load(sma, 0, kh, vh, 0, tid);
    cp_commit();

    {
        const uint32_t* qgh = g_qhi + ((size_t)bh * S_ + qbase) * 32;
        for (int idx = tid; idx < 1024; idx += 256) {
            int r = idx >> 3, c4 = (idx & 7) * 4;
            *(uint4*)&sPh[r * APS + c4] = *(const uint4*)(qgh + r * 32 + c4);
        }
        for (int idx = tid; idx < S_; idx += 256)
            sMf[idx] = (amask[b * S_ + idx] == 0) ? -INFINITY : 0.f;
    }
    __syncthreads();

    uint32_t Qh[4][4];
    #pragma unroll
    for (int ks = 0; ks < 4; ks++) {
        const uint32_t qaddr = smB + (((wrow + aR) * APS + ks * 8 + aC) << 2);
        ldsm4(Qh[ks], qaddr);
    }

    float oacc[8][4];
    #pragma unroll
    for (int nt = 0; nt < 8; nt++)
        #pragma unroll
        for (int r = 0; r < 4; r++) oacc[nt][r] = 0.f;
    float mrun[2] = {-INFINITY, -INFINITY};
    float lrun[2] = {0.f, 0.f};

    for (int kt = 0; kt < nkt; kt++) {
        if (kt + 1 < nkt) {
            attn_stage_load(sma, (kt + 1) & 1, kh, vh, kt + 1, tid);
            cp_commit();
            cp_wait<1>();
        } else {
            cp_wait<0>();
        }
        __syncthreads();

        if (kt * 64 <= qbase + wrow + 15) {
            const uint32_t kvB = smB + ((A_KV + (kt & 1) * KV_STAGE) << 2);

            // ---- S = Q K^T ----
            float sacc[8][4];
            #pragma unroll
            for (int nt = 0; nt < 8; nt++)
                #pragma unroll
                for (int r = 0; r < 4; r++) sacc[nt][r] = 0.f;

            #pragma unroll
            for (int ks = 0; ks < 4; ks++) {
                uint32_t bb[4][4];
                #pragma unroll
                for (int ntp = 0; ntp < 4; ntp++)
                    ldsm4(bb[ntp], kvB + ((KV_KH + (ntp * 16 + bR) * APS + ks * 8 + bC) << 2));
                #pragma unroll
                for (int ntp = 0; ntp < 4; ntp++) {
                    mma_f16(sacc[2 * ntp],     Qh[ks], bb[ntp]);
                    mma_f16(sacc[2 * ntp + 1], Qh[ks], bb[ntp] + 2);
                }
            }

            // ---- masks + row max (log2 domain) ----
            const bool diag = (kt * 64 + 63) > (qbase + wrow);
            float tmax[2] = {-INFINITY, -INFINITY};
            #pragma unroll
            for (int nt = 0; nt < 8; nt++) {
                #pragma unroll
                for (int e = 0; e < 4; e++) {
                    const int colL = nt * 8 + t * 2 + (e & 1);
                    float v = sacc[nt][e] + sMf[kt * 64 + colL];
                    if (diag) {
                        const int row = qbase + wrow + g + ((e >> 1) << 3);
                        const int col = kt * 64 + colL;
                        if (col > row) v = -INFINITY;
                    }
                    sacc[nt][e] = v;
                    tmax[e >> 1] = fmaxf(tmax[e >> 1], v);
                }
            }
            #pragma unroll
            for (int i = 0; i < 2; i++) {
                tmax[i] = fmaxf(tmax[i], __shfl_xor_sync(0xffffffff, tmax[i], 1));
                tmax[i] = fmaxf(tmax[i], __shfl_xor_sync(0xffffffff, tmax[i], 2));
            }

            // ---- online softmax (base-2); pack P-hi frags IN REGISTERS over sacc ----
            float corr[2], psum[2] = {0.f, 0.f};
            #pragma unroll
            for (int i = 0; i < 2; i++) {
                float mnew = fmaxf(mrun[i], tmax[i]);
                corr[i] = fexp2(mrun[i] - mnew);
                mrun[i] = mnew;
                lrun[i] *= corr[i];
            }
            #pragma unroll
            for (int nt = 0; nt < 8; nt++) {
                oacc[nt][0] *= corr[0]; oacc[nt][1] *= corr[0];
                oacc[nt][2] *= corr[1]; oacc[nt][3] *= corr[1];
            }
            #pragma unroll
            for (int nt = 0; nt < 8; nt++) {
                #pragma unroll
                for (int half = 0; half < 2; half++) {
                    float p0 = fexp2(sacc[nt][half * 2 + 0] - mrun[half]);
                    float p1 = fexp2(sacc[nt][half * 2 + 1] - mrun[half]);
                    psum[half] += p0 + p1;
                    sacc[nt][half * 2] = __uint_as_float(packh(p0, p1));
                }
            }
            #pragma unroll
            for (int i = 0; i < 2; i++) {
                psum[i] += __shfl_xor_sync(0xffffffff, psum[i], 1);
                psum[i] += __shfl_xor_sync(0xffffffff, psum[i], 2);
                lrun[i] += psum[i];
            }

            // ---- O += P V  (P-hi frags from registers; V trans frags) ----
            #pragma unroll
            for (int ks = 0; ks < 4; ks++) {
                uint32_t ph4[4];
                ph4[0] = __float_as_uint(sacc[2 * ks][0]);
                ph4[1] = __float_as_uint(sacc[2 * ks][2]);
                ph4[2] = __float_as_uint(sacc[2 * ks + 1][0]);
                ph4[3] = __float_as_uint(sacc[2 * ks + 1][2]);
                uint32_t vv[4][4];
                #pragma unroll
                for (int ntp = 0; ntp < 4; ntp++)
                    ldsm4t(vv[ntp], kvB + ((KV_VH + (ks * 16 + vR) * APS + ntp * 8 + vC) << 2));
                #pragma unroll
                for (int ntp = 0; ntp < 4; ntp++) {
                    mma_f16(oacc[2 * ntp],     ph4, vv[ntp]);
                    mma_f16(oacc[2 * ntp + 1], ph4, vv[ntp] + 2);
                }
            }
        }
        __syncthreads();
    }

    // ---- epilogue: o/l, fp16 quantize, packed write (hi only) ----
    const float inv0 = 1.f / lrun[0];
    const float inv1 = 1.f / lrun[1];
    const int r0 = qbase + wrow + g;
    const int r1 = r0 + 8;
    #pragma unroll
    for (int nt = 0; nt < 8; nt++) {
        const size_t o0 = (size_t)(b * S_ + r0) * 512 + h * 32 + nt * 4 + t;
        const size_t o1 = (size_t)(b * S_ + r1) * 512 + h * 32 + nt * 4 + t;
        g_yhi[o0] = packh(oacc[nt][0] * inv0, oacc[nt][1] * inv0);
        g_yhi[o1] = packh(oacc[nt][2] * inv1, oacc[nt][3] * inv1);
    }
}

// ---------------- launch ----------------
extern "C" void kernel_launch(void* const* d_in, const int* in_sizes, int n_in,
                              void* d_out, int out_size)
{
    const float* x     = (const float*)d_in[0];
    const float* w_qkv = (const float*)d_in[1];
    const float* w_o   = (const float*)d_in[2];
    const int*   amask = (const int*)d_in[3];
    float* out = (float*)d_out;

    uint32_t *xhi, *wqh, *woh, *yhi;
    cudaGetSymbolAddress((void**)&xhi, g_xhi);
    cudaGetSymbolAddress((void**)&wqh, g_wqh);
    cudaGetSymbolAddress((void**)&woh, g_woh);
    cudaGetSymbolAddress((void**)&yhi, g_yhi);

    const int smem_gemm = SMEM_GEMM_U32 * 4;
    cudaFuncSetAttribute(qkv_gemm_rope_kernel,
                         cudaFuncAttributeMaxDynamicSharedMemorySize, smem_gemm);
    cudaFuncSetAttribute(f16_gemm_kernel,
                         cudaFuncAttributeMaxDynamicSharedMemorySize, smem_gemm);
    const int smem_attn = SMEM_ATTN_U32 * 4;
    cudaFuncSetAttribute(attn_tc_kernel,
                         cudaFuncAttributeMaxDynamicSharedMemorySize, smem_attn);

    rope_table_kernel<<<256, 256>>>();

    quant2_kernel<<<(B_*S_*D_/2 + 255) / 256, 256>>>(x, xhi, B_*S_*D_/2);
    wsplit_t_kernel<<<dim3(3*D_/32, D_/32), 256>>>(w_qkv, wqh, D_, 3*D_);
    wsplit_t_kernel<<<dim3(D_/32, D_/32), 256>>>(w_o, woh, D_, D_);

    // QKV = x @ w_qkv with fused RoPE + quantize epilogue
    qkv_gemm_rope_kernel<<<dim3(3*D_/128, B_*S_/128), 256, smem_gemm>>>(xhi, wqh);

    attn_tc_kernel<<<(S_/128) * B_ * H_, 256, smem_attn>>>(amask);

    // out = y @ w_o
    f16_gemm_kernel<<<dim3(D_/128, B_*S_/128), 256, smem_gemm>>>(
        yhi, woh, out, B_*S_, D_, D_);
}